// round 1
// baseline (speedup 1.0000x reference)
#include <cuda_runtime.h>
#include <math.h>

// Problem constants
#define NB 2
#define NT 2048
#define NH 16
#define HD 64
#define NC 1024
#define PAD 68   // smem row pad (floats): 68*4B = 272B, 16B-aligned rows, conflict-reducing

// Scratch (allocation-free rule: __device__ globals)
__device__ __align__(16) float g_Q[NB*NH*NT*HD];
__device__ __align__(16) float g_K[NB*NH*NT*HD];
__device__ __align__(16) float g_V[NB*NH*NT*HD];
__device__ __align__(16) float g_O[NB*NH*NT*HD];
__device__ __align__(16) float g_Yn[NB*NT*NC];
__device__ __align__(16) float g_gpow[NH*NT];   // gamma_h^diff * 0.125 (1/sqrt(64) folded in)

// ---------------------------------------------------------------------------
// Decay table: gpow[h][diff] = gamma_h^diff / sqrt(D)
// ---------------------------------------------------------------------------
__global__ void gpow_kernel() {
    int idx = blockIdx.x * blockDim.x + threadIdx.x;
    if (idx >= NH * NT) return;
    int h = idx >> 11;
    int diff = idx & (NT - 1);
    double gamma = 1.0 - exp2(-5.0 - 0.5 * (double)h);
    g_gpow[idx] = (float)(exp2((double)diff * log2(gamma)) * 0.125);
}

// ---------------------------------------------------------------------------
// NT-GEMM: C[r,n] = sum_k A[r,k] * W[n,k]   (both operands K-major, torch Linear)
// 64x64 block tile, TK=16, 256 threads, 4x4 microtile.
// SPLIT=true writes into (B,H,T,D) head-split layout; else row-major (M,N).
// ---------------------------------------------------------------------------
template<bool SPLIT>
__global__ __launch_bounds__(256) void gemm_nt(const float* __restrict__ A,
                                               const float* __restrict__ W,
                                               float* __restrict__ Cout,
                                               int N, int K) {
    __shared__ float As[16 * PAD];   // As[k][i]
    __shared__ float Bs[16 * PAD];   // Bs[k][j]
    const int tid = threadIdx.x;
    const int r0 = blockIdx.x * 64;
    const int n0 = blockIdx.y * 64;
    const int tx = tid & 15, ty = tid >> 4;
    const int li = tid >> 2, lk = (tid & 3) * 4;

    float acc[16];
#pragma unroll
    for (int i = 0; i < 16; i++) acc[i] = 0.f;

    const float* Ap = A + (size_t)(r0 + li) * K + lk;
    const float* Wp = W + (size_t)(n0 + li) * K + lk;

    for (int k0 = 0; k0 < K; k0 += 16) {
        float4 av = *(const float4*)(Ap + k0);
        float4 bv = *(const float4*)(Wp + k0);
        __syncthreads();
        As[(lk+0)*PAD+li] = av.x; As[(lk+1)*PAD+li] = av.y;
        As[(lk+2)*PAD+li] = av.z; As[(lk+3)*PAD+li] = av.w;
        Bs[(lk+0)*PAD+li] = bv.x; Bs[(lk+1)*PAD+li] = bv.y;
        Bs[(lk+2)*PAD+li] = bv.z; Bs[(lk+3)*PAD+li] = bv.w;
        __syncthreads();
#pragma unroll
        for (int kk = 0; kk < 16; kk++) {
            float4 a  = *(const float4*)(As + kk*PAD + ty*4);
            float4 bb = *(const float4*)(Bs + kk*PAD + tx*4);
            float ar[4] = {a.x, a.y, a.z, a.w};
            float br[4] = {bb.x, bb.y, bb.z, bb.w};
#pragma unroll
            for (int ii = 0; ii < 4; ii++)
#pragma unroll
                for (int jj = 0; jj < 4; jj++)
                    acc[ii*4+jj] += ar[ii] * br[jj];
        }
    }

#pragma unroll
    for (int ii = 0; ii < 4; ii++) {
        int r = r0 + ty*4 + ii;
#pragma unroll
        for (int jj = 0; jj < 4; jj++) {
            int n = n0 + tx*4 + jj;
            float v = acc[ii*4+jj];
            if (SPLIT) {
                int bb = r >> 11, t = r & (NT - 1);
                int hh = n >> 6, d = n & 63;
                Cout[(((size_t)bb*NH + hh)*NT + t)*HD + d] = v;
            } else {
                Cout[(size_t)r * N + n] = v;
            }
        }
    }
}

// ---------------------------------------------------------------------------
// Causal retention: O[t,:] = sum_{s<=t} gamma^(t-s)/8 * (q_t . k_s) * v_s
// One block = one (b,h, 64-row t-tile). Loops over s-tiles <= t-tile.
// Stage 1: S = Q K^T * decay  (staged to smem, stored transposed)
// Stage 2: O += S V
// t-tiles scheduled largest-first to avoid causal-triangle tail.
// ---------------------------------------------------------------------------
__global__ __launch_bounds__(256) void retention_kernel() {
    extern __shared__ float sm[];
    float* Qs = sm;                         // [64][PAD]  Qs[d][i]
    float* Ks = sm + 64*PAD;                // [64][PAD]  Ks[d][j]
    float* St = sm + 2*64*PAD;              // [64][PAD]  St[j][i] = S[i][j]
    float* Vs = sm + 3*64*PAD;              // [64][64]   Vs[j][d]
    float* dw = sm + 3*64*PAD + 64*64;      // [128] decay window

    const int tid = threadIdx.x;
    const int bh  = blockIdx.y;
    const int h   = bh & (NH - 1);
    const int t0  = ((int)gridDim.x - 1 - (int)blockIdx.x) * 64;  // big tiles first

    const float* Qb = g_Q + (size_t)bh * NT * HD;
    const float* Kb = g_K + (size_t)bh * NT * HD;
    const float* Vb = g_V + (size_t)bh * NT * HD;
    const float* gp = g_gpow + h * NT;

    const int li  = tid >> 2;
    const int ld4 = (tid & 3) * 4;
    const int tx = tid & 15, ty = tid >> 4;
    const int i0 = ty * 4, j0 = tx * 4;

    // Load Q tile (transposed to d-major)
#pragma unroll
    for (int u = 0; u < 4; u++) {
        int d = ld4 + u * 16;
        float4 q = *(const float4*)(Qb + (size_t)(t0 + li) * HD + d);
        Qs[(d+0)*PAD+li] = q.x; Qs[(d+1)*PAD+li] = q.y;
        Qs[(d+2)*PAD+li] = q.z; Qs[(d+3)*PAD+li] = q.w;
    }

    float oacc[16];
#pragma unroll
    for (int i = 0; i < 16; i++) oacc[i] = 0.f;

    for (int s0 = 0; s0 <= t0; s0 += 64) {
        __syncthreads();  // previous stage-2 done before overwriting Ks/Vs/dw
#pragma unroll
        for (int u = 0; u < 4; u++) {
            int d = ld4 + u * 16;
            float4 k = *(const float4*)(Kb + (size_t)(s0 + li) * HD + d);
            Ks[(d+0)*PAD+li] = k.x; Ks[(d+1)*PAD+li] = k.y;
            Ks[(d+2)*PAD+li] = k.z; Ks[(d+3)*PAD+li] = k.w;
            float4 v = *(const float4*)(Vb + (size_t)(s0 + li) * HD + d);
            *(float4*)(Vs + li * 64 + d) = v;
        }
        if (tid < 128) {
            int diff = t0 - s0 - 63 + tid;
            dw[tid] = (diff >= 0 && diff < NT) ? gp[diff] : 0.f;  // zeros = causal mask
        }
        __syncthreads();

        // Stage 1: S[i][j] = sum_d Q[i][d] K[j][d]
        float sacc[16];
#pragma unroll
        for (int i = 0; i < 16; i++) sacc[i] = 0.f;
#pragma unroll 16
        for (int kk = 0; kk < 64; kk++) {
            float4 a = *(const float4*)(Qs + kk*PAD + i0);
            float4 b = *(const float4*)(Ks + kk*PAD + j0);
            float ar[4] = {a.x, a.y, a.z, a.w};
            float br[4] = {b.x, b.y, b.z, b.w};
#pragma unroll
            for (int jj = 0; jj < 4; jj++)
#pragma unroll
                for (int ii = 0; ii < 4; ii++)
                    sacc[jj*4+ii] += ar[ii] * br[jj];
        }
        // decay multiply + transposed store
#pragma unroll
        for (int jj = 0; jj < 4; jj++) {
            float4 sv;
            sv.x = sacc[jj*4+0] * dw[63 + (i0+0) - (j0+jj)];
            sv.y = sacc[jj*4+1] * dw[63 + (i0+1) - (j0+jj)];
            sv.z = sacc[jj*4+2] * dw[63 + (i0+2) - (j0+jj)];
            sv.w = sacc[jj*4+3] * dw[63 + (i0+3) - (j0+jj)];
            *(float4*)(St + (j0+jj)*PAD + i0) = sv;
        }
        __syncthreads();

        // Stage 2: O[i][d] += sum_j S[i][j] V[j][d]
#pragma unroll 16
        for (int kk = 0; kk < 64; kk++) {
            float4 a = *(const float4*)(St + kk*PAD + i0);   // S[i0..i0+3][kk]
            float4 b = *(const float4*)(Vs + kk*64 + j0);    // V[kk][d0..d0+3]
            float ar[4] = {a.x, a.y, a.z, a.w};
            float br[4] = {b.x, b.y, b.z, b.w};
#pragma unroll
            for (int ii = 0; ii < 4; ii++)
#pragma unroll
                for (int dd = 0; dd < 4; dd++)
                    oacc[ii*4+dd] += ar[ii] * br[dd];
        }
    }

    float* Ob = g_O + (size_t)bh * NT * HD;
#pragma unroll
    for (int ii = 0; ii < 4; ii++) {
        float4 ov = make_float4(oacc[ii*4+0], oacc[ii*4+1], oacc[ii*4+2], oacc[ii*4+3]);
        *(float4*)(Ob + (size_t)(t0 + i0 + ii) * HD + j0) = ov;
    }
}

// ---------------------------------------------------------------------------
// GroupNorm over (D,T) per (b,h); writes into (B,T,C) layout for final GEMM.
// ---------------------------------------------------------------------------
__global__ __launch_bounds__(256) void groupnorm_kernel(const float* __restrict__ O,
                                                        const float* __restrict__ gnw,
                                                        const float* __restrict__ gnb,
                                                        float* __restrict__ Yn) {
    const int bh = blockIdx.x;
    const int b = bh >> 4, h = bh & 15;
    const float* base = O + (size_t)bh * (NT * HD);
    const int tid = threadIdx.x;

    double s1 = 0.0, s2 = 0.0;
    for (int i = tid; i < NT * HD; i += 256) {
        float v = base[i];
        s1 += v;
        s2 += (double)v * v;
    }
    __shared__ double r1[256], r2[256];
    r1[tid] = s1; r2[tid] = s2;
    __syncthreads();
    for (int s = 128; s > 0; s >>= 1) {
        if (tid < s) { r1[tid] += r1[tid + s]; r2[tid] += r2[tid + s]; }
        __syncthreads();
    }
    __shared__ float smu, srs;
    if (tid == 0) {
        double mu  = r1[0] / (double)(NT * HD);
        double var = r2[0] / (double)(NT * HD) - mu * mu;
        smu = (float)mu;
        srs = (float)(1.0 / sqrt(var + 1e-5));
    }
    __syncthreads();
    float mu = smu, rs = srs;
    for (int i = tid; i < NT * HD; i += 256) {
        int t = i >> 6, d = i & 63;
        int c = h * 64 + d;
        float v = (base[i] - mu) * rs * gnw[c] + gnb[c];
        Yn[((size_t)b * NT + t) * NC + c] = v;
    }
}

// ---------------------------------------------------------------------------
// Launch
// ---------------------------------------------------------------------------
extern "C" void kernel_launch(void* const* d_in, const int* in_sizes, int n_in,
                              void* d_out, int out_size) {
    const float* x   = (const float*)d_in[0];
    const float* Wq  = (const float*)d_in[1];
    const float* Wk  = (const float*)d_in[2];
    const float* Wv  = (const float*)d_in[3];
    const float* Wo  = (const float*)d_in[4];
    const float* gnw = (const float*)d_in[5];
    const float* gnb = (const float*)d_in[6];
    float* out = (float*)d_out;

    float *gQ, *gK, *gV, *gO, *gYn;
    cudaGetSymbolAddress((void**)&gQ,  g_Q);
    cudaGetSymbolAddress((void**)&gK,  g_K);
    cudaGetSymbolAddress((void**)&gV,  g_V);
    cudaGetSymbolAddress((void**)&gO,  g_O);
    cudaGetSymbolAddress((void**)&gYn, g_Yn);

    gpow_kernel<<<(NH * NT + 255) / 256, 256>>>();

    dim3 gg(64, 16);  // (M/64, N/64) for M=4096, N=1024
    gemm_nt<true><<<gg, 256>>>(x, Wq, gQ, NC, NC);
    gemm_nt<true><<<gg, 256>>>(x, Wk, gK, NC, NC);
    gemm_nt<true><<<gg, 256>>>(x, Wv, gV, NC, NC);

    int smem = (3 * 64 * PAD + 64 * 64 + 128) * (int)sizeof(float);
    cudaFuncSetAttribute(retention_kernel,
                         cudaFuncAttributeMaxDynamicSharedMemorySize, smem);
    retention_kernel<<<dim3(NT / 64, NB * NH), 256, smem>>>();

    groupnorm_kernel<<<NB * NH, 256>>>(gO, gnw, gnb, gYn);

    gemm_nt<false><<<gg, 256>>>(gYn, Wo, out, NC, NC);
}

// round 4
// speedup vs baseline: 1.3802x; 1.3802x over previous
#include <cuda_runtime.h>
#include <cuda_bf16.h>
#include <math.h>
#include <cstdint>

#define NB 2
#define NT 2048
#define NH 16
#define HD 64
#define NC 1024
#define MTOT (NB*NT)   // 4096

typedef __nv_bfloat16  bf16;
typedef __nv_bfloat162 bf162;

// ---------------------------------------------------------------------------
// Scratch (allocation-free rule: __device__ globals)
// ---------------------------------------------------------------------------
__device__ __align__(16) bf16 g_Xh[MTOT*NC],  g_Xl[MTOT*NC];
__device__ __align__(16) bf16 g_Wh[4*NC*NC],  g_Wl[4*NC*NC];
__device__ __align__(16) bf16 g_Qh[NB*NH*NT*HD], g_Ql[NB*NH*NT*HD];
__device__ __align__(16) bf16 g_Kh[NB*NH*NT*HD], g_Kl[NB*NH*NT*HD];
__device__ __align__(16) bf16 g_Vh[NB*NH*NT*HD], g_Vl[NB*NH*NT*HD];
__device__ __align__(16) float g_O[NB*NH*NT*HD];
__device__ __align__(16) bf16 g_Ynh[MTOT*NC], g_Ynl[MTOT*NC];
__device__ float g_gpow[NH*NT];   // gamma_h^diff / sqrt(64)

// ---------------------------------------------------------------------------
// Helpers
// ---------------------------------------------------------------------------
__device__ __forceinline__ uint32_t smaddr(const void* p) {
    uint32_t a;
    asm("{ .reg .u64 t; cvta.to.shared.u64 t, %1; cvt.u32.u64 %0, t; }"
        : "=r"(a) : "l"(p));
    return a;
}
__device__ __forceinline__ void ldsm4(uint32_t r[4], uint32_t a) {
    asm volatile("ldmatrix.sync.aligned.m8n8.x4.shared.b16 {%0,%1,%2,%3}, [%4];"
        : "=r"(r[0]), "=r"(r[1]), "=r"(r[2]), "=r"(r[3]) : "r"(a));
}
__device__ __forceinline__ void ldsm4t(uint32_t r[4], uint32_t a) {
    asm volatile("ldmatrix.sync.aligned.m8n8.x4.trans.shared.b16 {%0,%1,%2,%3}, [%4];"
        : "=r"(r[0]), "=r"(r[1]), "=r"(r[2]), "=r"(r[3]) : "r"(a));
}
__device__ __forceinline__ void mma_bf(float c[4], const uint32_t a[4], const uint32_t b[2]) {
    asm volatile(
        "mma.sync.aligned.m16n8k16.row.col.f32.bf16.bf16.f32 "
        "{%0,%1,%2,%3}, {%4,%5,%6,%7}, {%8,%9}, {%0,%1,%2,%3};"
        : "+f"(c[0]), "+f"(c[1]), "+f"(c[2]), "+f"(c[3])
        : "r"(a[0]), "r"(a[1]), "r"(a[2]), "r"(a[3]), "r"(b[0]), "r"(b[1]));
}
__device__ __forceinline__ uint32_t pk2(float a, float b) {
    bf162 t = __floats2bfloat162_rn(a, b);
    return *reinterpret_cast<uint32_t*>(&t);
}

// ---------------------------------------------------------------------------
// Decay table
// ---------------------------------------------------------------------------
__global__ void gpow_kernel() {
    int idx = blockIdx.x * blockDim.x + threadIdx.x;
    if (idx >= NH * NT) return;
    int h = idx >> 11;
    int diff = idx & (NT - 1);
    double gamma = 1.0 - exp2(-5.0 - 0.5 * (double)h);
    g_gpow[idx] = (float)(exp2((double)diff * log2(gamma)) * 0.125);
}

// ---------------------------------------------------------------------------
// Split fp32 -> (hi, lo) bf16
// ---------------------------------------------------------------------------
__global__ void split_x_kernel(const float* __restrict__ src) {
    int i = blockIdx.x * blockDim.x + threadIdx.x;
    int stride = gridDim.x * blockDim.x;
    for (; i < MTOT * NC; i += stride) {
        float x = src[i];
        bf16 h = __float2bfloat16(x);
        g_Xh[i] = h;
        g_Xl[i] = __float2bfloat16(x - __bfloat162float(h));
    }
}
__global__ void split_w_kernel(const float* __restrict__ src, int widx) {
    int i = blockIdx.x * blockDim.x + threadIdx.x;
    int stride = gridDim.x * blockDim.x;
    bf16* dh = g_Wh + (size_t)widx * NC * NC;
    bf16* dl = g_Wl + (size_t)widx * NC * NC;
    for (; i < NC * NC; i += stride) {
        float x = src[i];
        bf16 h = __float2bfloat16(x);
        dh[i] = h;
        dl[i] = __float2bfloat16(x - __bfloat162float(h));
    }
}

// ---------------------------------------------------------------------------
// bf16x3 GEMM: C[r,n] = sum_k A[r,k]*W[n,k]  (both k-contiguous -> .row.col)
// Block 128x128, 8 warps (4x2), warp tile 32x64, k-chunk 32, double-buffered.
// ---------------------------------------------------------------------------
#define AST 40           // smem row stride in bf16 (80B, conflict-free)
#define KCH 32           // number of 32-wide k-chunks (K=1024)
#define SOA(buf,p) ((buf)*20480 + (p)*10240)
#define SOB(buf,p) (40960 + (buf)*20480 + (p)*10240)
#define GEMM_SMEM 81920

template<int MODE>
__global__ __launch_bounds__(256) void gemm_mma(float* __restrict__ Cf) {
    extern __shared__ __align__(16) char sm[];
    const int tid = threadIdx.x, l = tid & 31, wid = tid >> 5;
    const int wm = wid & 3, wn = wid >> 2;
    const int r0 = blockIdx.x * 128, n0 = blockIdx.y * 128;
    const int z = blockIdx.z;
    const int wsel = (MODE == 0) ? z : 3;

    const bf16* Ah = (MODE == 0) ? g_Xh : g_Ynh;
    const bf16* Al = (MODE == 0) ? g_Xl : g_Ynl;
    const bf16* Wh = g_Wh + (size_t)wsel * NC * NC;
    const bf16* Wl = g_Wl + (size_t)wsel * NC * NC;
    const uint32_t sb = smaddr(sm);

    float acc[2][8][4];
#pragma unroll
    for (int mi = 0; mi < 2; mi++)
#pragma unroll
        for (int ni = 0; ni < 8; ni++)
#pragma unroll
            for (int q = 0; q < 4; q++) acc[mi][ni][q] = 0.f;

    // preload chunk 0
#pragma unroll
    for (int p = 0; p < 2; p++) {
        const bf16* Ap = p ? Al : Ah;
        const bf16* Wp = p ? Wl : Wh;
#pragma unroll
        for (int i = 0; i < 2; i++) {
            int flat = tid + 256 * i;
            int row = flat >> 2, seg = flat & 3;
            uint4 va = *(const uint4*)(Ap + (size_t)(r0 + row) * NC + seg * 8);
            *(uint4*)(sm + SOA(0, p) + (row * AST + seg * 8) * 2) = va;
            uint4 vb = *(const uint4*)(Wp + (size_t)(n0 + row) * NC + seg * 8);
            *(uint4*)(sm + SOB(0, p) + (row * AST + seg * 8) * 2) = vb;
        }
    }
    __syncthreads();

    uint4 stA[2][2], stB[2][2];
    for (int c = 0; c < KCH; c++) {
        const int buf = c & 1;
        const bool pre = (c + 1 < KCH);
        if (pre) {
            const int kb = (c + 1) * 32;
#pragma unroll
            for (int p = 0; p < 2; p++) {
                const bf16* Ap = p ? Al : Ah;
                const bf16* Wp = p ? Wl : Wh;
#pragma unroll
                for (int i = 0; i < 2; i++) {
                    int flat = tid + 256 * i;
                    int row = flat >> 2, seg = flat & 3;
                    stA[p][i] = *(const uint4*)(Ap + (size_t)(r0 + row) * NC + kb + seg * 8);
                    stB[p][i] = *(const uint4*)(Wp + (size_t)(n0 + row) * NC + kb + seg * 8);
                }
            }
        }
        // compute this chunk (two k16 steps)
#pragma unroll
        for (int ks = 0; ks < 32; ks += 16) {
            uint32_t af[2][2][4];
#pragma unroll
            for (int p = 0; p < 2; p++)
#pragma unroll
                for (int mi = 0; mi < 2; mi++) {
                    int row = wm * 32 + mi * 16 + (l & 7) + ((l >> 3) & 1) * 8;
                    int col = ks + (l >> 4) * 8;
                    ldsm4(af[p][mi], sb + SOA(buf, p) + (row * AST + col) * 2);
                }
            uint32_t bfr[2][8][2];
#pragma unroll
            for (int p = 0; p < 2; p++)
#pragma unroll
                for (int na = 0; na < 4; na++) {
                    int row = wn * 64 + na * 16 + (l >> 4) * 8 + (l & 7);
                    int col = ks + ((l >> 3) & 1) * 8;
                    uint32_t r4[4];
                    ldsm4(r4, sb + SOB(buf, p) + (row * AST + col) * 2);
                    bfr[p][na * 2][0] = r4[0]; bfr[p][na * 2][1] = r4[1];
                    bfr[p][na * 2 + 1][0] = r4[2]; bfr[p][na * 2 + 1][1] = r4[3];
                }
#pragma unroll
            for (int mi = 0; mi < 2; mi++)
#pragma unroll
                for (int ni = 0; ni < 8; ni++) mma_bf(acc[mi][ni], af[0][mi], bfr[0][ni]);
#pragma unroll
            for (int mi = 0; mi < 2; mi++)
#pragma unroll
                for (int ni = 0; ni < 8; ni++) mma_bf(acc[mi][ni], af[0][mi], bfr[1][ni]);
#pragma unroll
            for (int mi = 0; mi < 2; mi++)
#pragma unroll
                for (int ni = 0; ni < 8; ni++) mma_bf(acc[mi][ni], af[1][mi], bfr[0][ni]);
        }
        if (pre) {
            const int nb2 = buf ^ 1;
#pragma unroll
            for (int p = 0; p < 2; p++)
#pragma unroll
                for (int i = 0; i < 2; i++) {
                    int flat = tid + 256 * i;
                    int row = flat >> 2, seg = flat & 3;
                    *(uint4*)(sm + SOA(nb2, p) + (row * AST + seg * 8) * 2) = stA[p][i];
                    *(uint4*)(sm + SOB(nb2, p) + (row * AST + seg * 8) * 2) = stB[p][i];
                }
        }
        __syncthreads();
    }

    // epilogue
    const int g = l >> 2, tq = l & 3;
    bf16* oh = nullptr; bf16* ol = nullptr;
    if (MODE == 0) {
        oh = (z == 0) ? g_Qh : (z == 1) ? g_Kh : g_Vh;
        ol = (z == 0) ? g_Ql : (z == 1) ? g_Kl : g_Vl;
    }
#pragma unroll
    for (int mi = 0; mi < 2; mi++)
#pragma unroll
        for (int ni = 0; ni < 8; ni++) {
            int rbase = r0 + wm * 32 + mi * 16 + g;
            int n = n0 + wn * 64 + ni * 8 + 2 * tq;
#pragma unroll
            for (int rr = 0; rr < 2; rr++) {
                int row = rbase + rr * 8;
                float v0 = acc[mi][ni][rr * 2 + 0];
                float v1 = acc[mi][ni][rr * 2 + 1];
                if (MODE == 0) {
                    int b = row >> 11, t = row & (NT - 1);
                    int hh = n >> 6, d = n & 63;
                    size_t idx = (((size_t)b * NH + hh) * NT + t) * HD + d;
                    bf16 h0 = __float2bfloat16(v0);
                    bf16 h1 = __float2bfloat16(v1);
                    bf162 hv; hv.x = h0; hv.y = h1;
                    bf162 lv;
                    lv.x = __float2bfloat16(v0 - __bfloat162float(h0));
                    lv.y = __float2bfloat16(v1 - __bfloat162float(h1));
                    *(bf162*)(oh + idx) = hv;
                    *(bf162*)(ol + idx) = lv;
                } else {
                    *(float2*)(Cf + (size_t)row * NC + n) = make_float2(v0, v1);
                }
            }
        }
}

// ---------------------------------------------------------------------------
// Retention with bf16x3 mma: per block one (b,h) and a 128-row t-tile.
// 8 warps, each computes a 16x64 stripe of S then of O. S stays in registers.
// s-loop covers s0 <= t0+64 (diagonal blocks for rows t0+64..t0+127); the
// decay window zeroes diff<0 entries, enforcing causality inside blocks.
// ---------------------------------------------------------------------------
#define RST 72                      // smem row stride (bf16), conflict-free
#define RQ(p)  ((p)*18432)
#define RK(p)  (36864 + (p)*9216)
#define RV(p)  (55296 + (p)*9216)
#define RDW    73728
#define RET_SMEM 74752

__global__ __launch_bounds__(256) void retention_mma() {
    extern __shared__ __align__(16) char sm[];
    float* dw = (float*)(sm + RDW);
    const int tid = threadIdx.x, l = tid & 31, wid = tid >> 5;
    const int bh = blockIdx.y;
    const int h = bh & (NH - 1);
    const int t0 = ((int)gridDim.x - 1 - (int)blockIdx.x) * 128;
    const uint32_t sb = smaddr(sm);
    const size_t base = (size_t)bh * NT * HD;
    const float* gp = g_gpow + h * NT;

    // load Q tile 128x64 (both parts)
#pragma unroll
    for (int p = 0; p < 2; p++) {
        const bf16* Qp = (p ? g_Ql : g_Qh) + base + (size_t)t0 * HD;
#pragma unroll
        for (int i = 0; i < 4; i++) {
            int flat = tid + 256 * i;
            int row = flat >> 3, seg = flat & 7;
            uint4 v = *(const uint4*)(Qp + (size_t)row * HD + seg * 8);
            *(uint4*)(sm + RQ(p) + (row * RST + seg * 8) * 2) = v;
        }
    }
    __syncthreads();

    // Q A-frags resident in registers: [part][k16][4]
    uint32_t aq[2][4][4];
#pragma unroll
    for (int p = 0; p < 2; p++)
#pragma unroll
        for (int kc = 0; kc < 4; kc++) {
            int row = wid * 16 + (l & 7) + ((l >> 3) & 1) * 8;
            int col = kc * 16 + (l >> 4) * 8;
            ldsm4(aq[p][kc], sb + RQ(p) + (row * RST + col) * 2);
        }

    float oacc[8][4];
#pragma unroll
    for (int ni = 0; ni < 8; ni++)
#pragma unroll
        for (int q = 0; q < 4; q++) oacc[ni][q] = 0.f;

    const int g = l >> 2, tq = l & 3;
    const int ibase = 16 * wid + g;

    for (int s0 = 0; s0 <= t0 + 64; s0 += 64) {   // include diagonal block of rows t0+64..t0+127
        __syncthreads();   // prior iteration done with K/V/dw
        // load K,V tiles 64x64 (both parts)
#pragma unroll
        for (int p = 0; p < 2; p++) {
            const bf16* Kp = (p ? g_Kl : g_Kh) + base + (size_t)s0 * HD;
            const bf16* Vp = (p ? g_Vl : g_Vh) + base + (size_t)s0 * HD;
#pragma unroll
            for (int i = 0; i < 2; i++) {
                int flat = tid + 256 * i;
                int row = flat >> 3, seg = flat & 7;
                uint4 kv = *(const uint4*)(Kp + (size_t)row * HD + seg * 8);
                *(uint4*)(sm + RK(p) + (row * RST + seg * 8) * 2) = kv;
                uint4 vv = *(const uint4*)(Vp + (size_t)row * HD + seg * 8);
                *(uint4*)(sm + RV(p) + (row * RST + seg * 8) * 2) = vv;
            }
        }
        if (tid < 192) {
            int diff = t0 - s0 - 63 + tid;
            dw[tid] = (diff >= 0 && diff < NT) ? gp[diff] : 0.f;
        }
        __syncthreads();

        // S = Q K^T (bf16x3)
        float sacc[8][4];
#pragma unroll
        for (int ni = 0; ni < 8; ni++)
#pragma unroll
            for (int q = 0; q < 4; q++) sacc[ni][q] = 0.f;
#pragma unroll
        for (int kc = 0; kc < 4; kc++) {
            uint32_t bk[2][8][2];
#pragma unroll
            for (int p = 0; p < 2; p++)
#pragma unroll
                for (int na = 0; na < 4; na++) {
                    int row = na * 16 + (l >> 4) * 8 + (l & 7);
                    int col = kc * 16 + ((l >> 3) & 1) * 8;
                    uint32_t r4[4];
                    ldsm4(r4, sb + RK(p) + (row * RST + col) * 2);
                    bk[p][na * 2][0] = r4[0]; bk[p][na * 2][1] = r4[1];
                    bk[p][na * 2 + 1][0] = r4[2]; bk[p][na * 2 + 1][1] = r4[3];
                }
#pragma unroll
            for (int ni = 0; ni < 8; ni++) mma_bf(sacc[ni], aq[0][kc], bk[0][ni]);
#pragma unroll
            for (int ni = 0; ni < 8; ni++) mma_bf(sacc[ni], aq[0][kc], bk[1][ni]);
#pragma unroll
            for (int ni = 0; ni < 8; ni++) mma_bf(sacc[ni], aq[1][kc], bk[0][ni]);
        }

        // decay multiply (dw zero => masked, enforces causality)
#pragma unroll
        for (int ni = 0; ni < 8; ni++) {
            int jb = ni * 8 + 2 * tq;
            sacc[ni][0] *= dw[63 + ibase - jb];
            sacc[ni][1] *= dw[63 + ibase - (jb + 1)];
            sacc[ni][2] *= dw[63 + ibase + 8 - jb];
            sacc[ni][3] *= dw[63 + ibase + 8 - (jb + 1)];
        }

        // split S into hi/lo A-frags (accumulator layout == A layout)
        uint32_t ash[4][4], asl[4][4];
#pragma unroll
        for (int kc = 0; kc < 4; kc++) {
            const float* e0 = sacc[2 * kc];
            const float* e1 = sacc[2 * kc + 1];
            float hv[8], lv[8];
            float src[8] = {e0[0], e0[1], e0[2], e0[3], e1[0], e1[1], e1[2], e1[3]};
#pragma unroll
            for (int q = 0; q < 8; q++) {
                bf16 hb = __float2bfloat16(src[q]);
                hv[q] = __bfloat162float(hb);
                lv[q] = src[q] - hv[q];
            }
            ash[kc][0] = pk2(hv[0], hv[1]); ash[kc][1] = pk2(hv[2], hv[3]);
            ash[kc][2] = pk2(hv[4], hv[5]); ash[kc][3] = pk2(hv[6], hv[7]);
            asl[kc][0] = pk2(lv[0], lv[1]); asl[kc][1] = pk2(lv[2], lv[3]);
            asl[kc][2] = pk2(lv[4], lv[5]); asl[kc][3] = pk2(lv[6], lv[7]);
        }

        // O += S V (bf16x3), V via ldmatrix.trans (B = V^T)
#pragma unroll
        for (int kc = 0; kc < 4; kc++) {
            uint32_t bv[2][8][2];
#pragma unroll
            for (int p = 0; p < 2; p++)
#pragma unroll
                for (int na = 0; na < 4; na++) {
                    int row = kc * 16 + ((l >> 3) & 1) * 8 + (l & 7);
                    int col = na * 16 + (l >> 4) * 8;
                    uint32_t r4[4];
                    ldsm4t(r4, sb + RV(p) + (row * RST + col) * 2);
                    bv[p][na * 2][0] = r4[0]; bv[p][na * 2][1] = r4[1];
                    bv[p][na * 2 + 1][0] = r4[2]; bv[p][na * 2 + 1][1] = r4[3];
                }
#pragma unroll
            for (int ni = 0; ni < 8; ni++) mma_bf(oacc[ni], ash[kc], bv[0][ni]);
#pragma unroll
            for (int ni = 0; ni < 8; ni++) mma_bf(oacc[ni], ash[kc], bv[1][ni]);
#pragma unroll
            for (int ni = 0; ni < 8; ni++) mma_bf(oacc[ni], asl[kc], bv[0][ni]);
        }
    }

    // write O (fp32)
#pragma unroll
    for (int ni = 0; ni < 8; ni++) {
        int col = ni * 8 + 2 * tq;
        int r1 = t0 + ibase, r2 = r1 + 8;
        *(float2*)(g_O + (base + (size_t)r1 * HD + col)) = make_float2(oacc[ni][0], oacc[ni][1]);
        *(float2*)(g_O + (base + (size_t)r2 * HD + col)) = make_float2(oacc[ni][2], oacc[ni][3]);
    }
}

// ---------------------------------------------------------------------------
// GroupNorm over (D,T) per (b,h); writes split bf16 into (B,T,C).
// ---------------------------------------------------------------------------
__global__ __launch_bounds__(256) void groupnorm_kernel(const float* __restrict__ gnw,
                                                        const float* __restrict__ gnb) {
    const int bh = blockIdx.x;
    const int b = bh >> 4, h = bh & 15;
    const float* bsrc = g_O + (size_t)bh * (NT * HD);
    const int tid = threadIdx.x;

    double s1 = 0.0, s2 = 0.0;
    for (int i = tid; i < NT * HD; i += 256) {
        float v = bsrc[i];
        s1 += v;
        s2 += (double)v * v;
    }
    __shared__ double r1[256], r2[256];
    r1[tid] = s1; r2[tid] = s2;
    __syncthreads();
    for (int s = 128; s > 0; s >>= 1) {
        if (tid < s) { r1[tid] += r1[tid + s]; r2[tid] += r2[tid + s]; }
        __syncthreads();
    }
    __shared__ float smu, srs;
    if (tid == 0) {
        double mu  = r1[0] / (double)(NT * HD);
        double var = r2[0] / (double)(NT * HD) - mu * mu;
        smu = (float)mu;
        srs = (float)(1.0 / sqrt(var + 1e-5));
    }
    __syncthreads();
    float mu = smu, rs = srs;
    for (int i = tid; i < NT * HD; i += 256) {
        int t = i >> 6, d = i & 63;
        int c = h * 64 + d;
        float v = (bsrc[i] - mu) * rs * gnw[c] + gnb[c];
        size_t idx = ((size_t)b * NT + t) * NC + c;
        bf16 hv = __float2bfloat16(v);
        g_Ynh[idx] = hv;
        g_Ynl[idx] = __float2bfloat16(v - __bfloat162float(hv));
    }
}

// ---------------------------------------------------------------------------
// Launch
// ---------------------------------------------------------------------------
extern "C" void kernel_launch(void* const* d_in, const int* in_sizes, int n_in,
                              void* d_out, int out_size) {
    const float* x   = (const float*)d_in[0];
    const float* Wq  = (const float*)d_in[1];
    const float* Wk  = (const float*)d_in[2];
    const float* Wv  = (const float*)d_in[3];
    const float* Wo  = (const float*)d_in[4];
    const float* gnw = (const float*)d_in[5];
    const float* gnb = (const float*)d_in[6];
    float* out = (float*)d_out;

    gpow_kernel<<<(NH * NT + 255) / 256, 256>>>();
    split_x_kernel<<<1024, 256>>>(x);
    split_w_kernel<<<512, 256>>>(Wq, 0);
    split_w_kernel<<<512, 256>>>(Wk, 1);
    split_w_kernel<<<512, 256>>>(Wv, 2);
    split_w_kernel<<<512, 256>>>(Wo, 3);

    cudaFuncSetAttribute(gemm_mma<0>, cudaFuncAttributeMaxDynamicSharedMemorySize, GEMM_SMEM);
    cudaFuncSetAttribute(gemm_mma<1>, cudaFuncAttributeMaxDynamicSharedMemorySize, GEMM_SMEM);
    cudaFuncSetAttribute(retention_mma, cudaFuncAttributeMaxDynamicSharedMemorySize, RET_SMEM);

    gemm_mma<0><<<dim3(MTOT / 128, NC / 128, 3), 256, GEMM_SMEM>>>(nullptr);
    retention_mma<<<dim3(NT / 128, NB * NH), 256, RET_SMEM>>>();
    groupnorm_kernel<<<NB * NH, 256>>>(gnw, gnb);
    gemm_mma<1><<<dim3(MTOT / 128, NC / 128, 1), 256, GEMM_SMEM>>>(out);
}

// round 5
// speedup vs baseline: 2.4231x; 1.7557x over previous
#include <cuda_runtime.h>
#include <cuda_bf16.h>
#include <math.h>
#include <cstdint>

#define NB 2
#define NT 2048
#define NH 16
#define HD 64
#define NC 1024
#define MTOT (NB*NT)   // 4096
#define NCHUNK 16      // T / 128

typedef __nv_bfloat16  bf16;
typedef __nv_bfloat162 bf162;

// ---------------------------------------------------------------------------
// Scratch (allocation-free rule: __device__ globals)
// ---------------------------------------------------------------------------
__device__ __align__(16) bf16 g_Xh[MTOT*NC],  g_Xl[MTOT*NC];
__device__ __align__(16) bf16 g_Wh[4*NC*NC],  g_Wl[4*NC*NC];
__device__ __align__(16) bf16 g_Qh[NB*NH*NT*HD], g_Ql[NB*NH*NT*HD];
__device__ __align__(16) bf16 g_Kh[NB*NH*NT*HD], g_Kl[NB*NH*NT*HD];
__device__ __align__(16) bf16 g_Vh[NB*NH*NT*HD], g_Vl[NB*NH*NT*HD];
__device__ __align__(16) float g_O[NB*NH*NT*HD];
__device__ __align__(16) bf16 g_Ynh[MTOT*NC], g_Ynl[MTOT*NC];
__device__ __align__(16) float g_U[NB*NH*NCHUNK*HD*HD];        // chunk summaries
__device__ __align__(16) bf16 g_Sth[NB*NH*NCHUNK*HD*HD];       // per-chunk states (hi)
__device__ __align__(16) bf16 g_Stl[NB*NH*NCHUNK*HD*HD];       // per-chunk states (lo)

// ---------------------------------------------------------------------------
// Helpers
// ---------------------------------------------------------------------------
__device__ __forceinline__ uint32_t smaddr(const void* p) {
    uint32_t a;
    asm("{ .reg .u64 t; cvta.to.shared.u64 t, %1; cvt.u32.u64 %0, t; }"
        : "=r"(a) : "l"(p));
    return a;
}
__device__ __forceinline__ void ldsm4(uint32_t r[4], uint32_t a) {
    asm volatile("ldmatrix.sync.aligned.m8n8.x4.shared.b16 {%0,%1,%2,%3}, [%4];"
        : "=r"(r[0]), "=r"(r[1]), "=r"(r[2]), "=r"(r[3]) : "r"(a));
}
__device__ __forceinline__ void ldsm4t(uint32_t r[4], uint32_t a) {
    asm volatile("ldmatrix.sync.aligned.m8n8.x4.trans.shared.b16 {%0,%1,%2,%3}, [%4];"
        : "=r"(r[0]), "=r"(r[1]), "=r"(r[2]), "=r"(r[3]) : "r"(a));
}
__device__ __forceinline__ void mma_bf(float c[4], const uint32_t a[4], const uint32_t b[2]) {
    asm volatile(
        "mma.sync.aligned.m16n8k16.row.col.f32.bf16.bf16.f32 "
        "{%0,%1,%2,%3}, {%4,%5,%6,%7}, {%8,%9}, {%0,%1,%2,%3};"
        : "+f"(c[0]), "+f"(c[1]), "+f"(c[2]), "+f"(c[3])
        : "r"(a[0]), "r"(a[1]), "r"(a[2]), "r"(a[3]), "r"(b[0]), "r"(b[1]));
}
__device__ __forceinline__ uint32_t pk2(float a, float b) {
    bf162 t = __floats2bfloat162_rn(a, b);
    return *reinterpret_cast<uint32_t*>(&t);
}
__device__ __forceinline__ float lg2gamma(int h) {
    double gamma = 1.0 - exp2(-5.0 - 0.5 * (double)h);
    return (float)log2(gamma);
}

// ---------------------------------------------------------------------------
// Split fp32 -> (hi, lo) bf16
// ---------------------------------------------------------------------------
__global__ void split_x_kernel(const float* __restrict__ src) {
    int i = blockIdx.x * blockDim.x + threadIdx.x;
    int stride = gridDim.x * blockDim.x;
    for (; i < MTOT * NC; i += stride) {
        float x = src[i];
        bf16 h = __float2bfloat16(x);
        g_Xh[i] = h;
        g_Xl[i] = __float2bfloat16(x - __bfloat162float(h));
    }
}
__global__ void split_w_kernel(const float* __restrict__ src, int widx) {
    int i = blockIdx.x * blockDim.x + threadIdx.x;
    int stride = gridDim.x * blockDim.x;
    bf16* dh = g_Wh + (size_t)widx * NC * NC;
    bf16* dl = g_Wl + (size_t)widx * NC * NC;
    for (; i < NC * NC; i += stride) {
        float x = src[i];
        bf16 h = __float2bfloat16(x);
        dh[i] = h;
        dl[i] = __float2bfloat16(x - __bfloat162float(h));
    }
}

// ---------------------------------------------------------------------------
// bf16x3 GEMM (unchanged from R4): C[r,n] = sum_k A[r,k]*W[n,k]
// ---------------------------------------------------------------------------
#define AST 40
#define KCH 32
#define SOA(buf,p) ((buf)*20480 + (p)*10240)
#define SOB(buf,p) (40960 + (buf)*20480 + (p)*10240)
#define GEMM_SMEM 81920

template<int MODE>
__global__ __launch_bounds__(256) void gemm_mma(float* __restrict__ Cf) {
    extern __shared__ __align__(16) char sm[];
    const int tid = threadIdx.x, l = tid & 31, wid = tid >> 5;
    const int wm = wid & 3, wn = wid >> 2;
    const int r0 = blockIdx.x * 128, n0 = blockIdx.y * 128;
    const int z = blockIdx.z;
    const int wsel = (MODE == 0) ? z : 3;

    const bf16* Ah = (MODE == 0) ? g_Xh : g_Ynh;
    const bf16* Al = (MODE == 0) ? g_Xl : g_Ynl;
    const bf16* Wh = g_Wh + (size_t)wsel * NC * NC;
    const bf16* Wl = g_Wl + (size_t)wsel * NC * NC;
    const uint32_t sb = smaddr(sm);

    float acc[2][8][4];
#pragma unroll
    for (int mi = 0; mi < 2; mi++)
#pragma unroll
        for (int ni = 0; ni < 8; ni++)
#pragma unroll
            for (int q = 0; q < 4; q++) acc[mi][ni][q] = 0.f;

#pragma unroll
    for (int p = 0; p < 2; p++) {
        const bf16* Ap = p ? Al : Ah;
        const bf16* Wp = p ? Wl : Wh;
#pragma unroll
        for (int i = 0; i < 2; i++) {
            int flat = tid + 256 * i;
            int row = flat >> 2, seg = flat & 3;
            uint4 va = *(const uint4*)(Ap + (size_t)(r0 + row) * NC + seg * 8);
            *(uint4*)(sm + SOA(0, p) + (row * AST + seg * 8) * 2) = va;
            uint4 vb = *(const uint4*)(Wp + (size_t)(n0 + row) * NC + seg * 8);
            *(uint4*)(sm + SOB(0, p) + (row * AST + seg * 8) * 2) = vb;
        }
    }
    __syncthreads();

    uint4 stA[2][2], stB[2][2];
    for (int c = 0; c < KCH; c++) {
        const int buf = c & 1;
        const bool pre = (c + 1 < KCH);
        if (pre) {
            const int kb = (c + 1) * 32;
#pragma unroll
            for (int p = 0; p < 2; p++) {
                const bf16* Ap = p ? Al : Ah;
                const bf16* Wp = p ? Wl : Wh;
#pragma unroll
                for (int i = 0; i < 2; i++) {
                    int flat = tid + 256 * i;
                    int row = flat >> 2, seg = flat & 3;
                    stA[p][i] = *(const uint4*)(Ap + (size_t)(r0 + row) * NC + kb + seg * 8);
                    stB[p][i] = *(const uint4*)(Wp + (size_t)(n0 + row) * NC + kb + seg * 8);
                }
            }
        }
#pragma unroll
        for (int ks = 0; ks < 32; ks += 16) {
            uint32_t af[2][2][4];
#pragma unroll
            for (int p = 0; p < 2; p++)
#pragma unroll
                for (int mi = 0; mi < 2; mi++) {
                    int row = wm * 32 + mi * 16 + (l & 7) + ((l >> 3) & 1) * 8;
                    int col = ks + (l >> 4) * 8;
                    ldsm4(af[p][mi], sb + SOA(buf, p) + (row * AST + col) * 2);
                }
            uint32_t bfr[2][8][2];
#pragma unroll
            for (int p = 0; p < 2; p++)
#pragma unroll
                for (int na = 0; na < 4; na++) {
                    int row = wn * 64 + na * 16 + (l >> 4) * 8 + (l & 7);
                    int col = ks + ((l >> 3) & 1) * 8;
                    uint32_t r4[4];
                    ldsm4(r4, sb + SOB(buf, p) + (row * AST + col) * 2);
                    bfr[p][na * 2][0] = r4[0]; bfr[p][na * 2][1] = r4[1];
                    bfr[p][na * 2 + 1][0] = r4[2]; bfr[p][na * 2 + 1][1] = r4[3];
                }
#pragma unroll
            for (int mi = 0; mi < 2; mi++)
#pragma unroll
                for (int ni = 0; ni < 8; ni++) mma_bf(acc[mi][ni], af[0][mi], bfr[0][ni]);
#pragma unroll
            for (int mi = 0; mi < 2; mi++)
#pragma unroll
                for (int ni = 0; ni < 8; ni++) mma_bf(acc[mi][ni], af[0][mi], bfr[1][ni]);
#pragma unroll
            for (int mi = 0; mi < 2; mi++)
#pragma unroll
                for (int ni = 0; ni < 8; ni++) mma_bf(acc[mi][ni], af[1][mi], bfr[0][ni]);
        }
        if (pre) {
            const int nb2 = buf ^ 1;
#pragma unroll
            for (int p = 0; p < 2; p++)
#pragma unroll
                for (int i = 0; i < 2; i++) {
                    int flat = tid + 256 * i;
                    int row = flat >> 2, seg = flat & 3;
                    *(uint4*)(sm + SOA(nb2, p) + (row * AST + seg * 8) * 2) = stA[p][i];
                    *(uint4*)(sm + SOB(nb2, p) + (row * AST + seg * 8) * 2) = stB[p][i];
                }
        }
        __syncthreads();
    }

    const int g = l >> 2, tq = l & 3;
    bf16* oh = nullptr; bf16* ol = nullptr;
    if (MODE == 0) {
        oh = (z == 0) ? g_Qh : (z == 1) ? g_Kh : g_Vh;
        ol = (z == 0) ? g_Ql : (z == 1) ? g_Kl : g_Vl;
    }
#pragma unroll
    for (int mi = 0; mi < 2; mi++)
#pragma unroll
        for (int ni = 0; ni < 8; ni++) {
            int rbase = r0 + wm * 32 + mi * 16 + g;
            int n = n0 + wn * 64 + ni * 8 + 2 * tq;
#pragma unroll
            for (int rr = 0; rr < 2; rr++) {
                int row = rbase + rr * 8;
                float v0 = acc[mi][ni][rr * 2 + 0];
                float v1 = acc[mi][ni][rr * 2 + 1];
                if (MODE == 0) {
                    int b = row >> 11, t = row & (NT - 1);
                    int hh = n >> 6, d = n & 63;
                    size_t idx = (((size_t)b * NH + hh) * NT + t) * HD + d;
                    bf16 h0 = __float2bfloat16(v0);
                    bf16 h1 = __float2bfloat16(v1);
                    bf162 hv; hv.x = h0; hv.y = h1;
                    bf162 lv;
                    lv.x = __float2bfloat16(v0 - __bfloat162float(h0));
                    lv.y = __float2bfloat16(v1 - __bfloat162float(h1));
                    *(bf162*)(oh + idx) = hv;
                    *(bf162*)(ol + idx) = lv;
                } else {
                    *(float2*)(Cf + (size_t)row * NC + n) = make_float2(v0, v1);
                }
            }
        }
}

// ---------------------------------------------------------------------------
// Phase A: per-chunk KV summary  U_c[dk][dv] = sum_j gamma^(cend-j) k_j[dk] v_j[dv]
// grid (NCHUNK, NB*NH), 128 threads (4 warps, warp handles 16 dk rows).
// ---------------------------------------------------------------------------
#define CST 72
#define CWK(p) ((p)*18432)
#define CV(p)  (36864 + (p)*18432)
#define CHUNK_SMEM 73728

__global__ __launch_bounds__(128) void chunk_state_kernel() {
    extern __shared__ __align__(16) char sm[];
    const int tid = threadIdx.x, l = tid & 31, wid = tid >> 5;
    const int ci = blockIdx.x, bh = blockIdx.y, h = bh & (NH - 1);
    const float lg = lg2gamma(h);
    const uint32_t sb = smaddr(sm);
    const size_t base = (size_t)bh * NT * HD + (size_t)ci * 128 * HD;

    // load + weight K, copy V (both hi/lo parts). One row per thread.
    {
        const int j = tid;
        const float w = exp2f(lg * (float)(127 - j));
        const bf16* Kh = g_Kh + base + (size_t)j * HD;
        const bf16* Kl = g_Kl + base + (size_t)j * HD;
        const bf16* Vh = g_Vh + base + (size_t)j * HD;
        const bf16* Vl = g_Vl + base + (size_t)j * HD;
#pragma unroll
        for (int seg = 0; seg < 8; seg++) {
            uint4 khv = *(const uint4*)(Kh + seg * 8);
            uint4 klv = *(const uint4*)(Kl + seg * 8);
            const bf162* kh2 = (const bf162*)&khv;
            const bf162* kl2 = (const bf162*)&klv;
            uint32_t oh[4], ol[4];
#pragma unroll
            for (int q = 0; q < 4; q++) {
                float f0 = __bfloat162float(kh2[q].x) + __bfloat162float(kl2[q].x);
                float f1 = __bfloat162float(kh2[q].y) + __bfloat162float(kl2[q].y);
                f0 *= w; f1 *= w;
                bf16 h0 = __float2bfloat16(f0), h1 = __float2bfloat16(f1);
                oh[q] = pk2(__bfloat162float(h0), __bfloat162float(h1));
                // re-split exactly
                float r0 = f0 - __bfloat162float(h0);
                float r1 = f1 - __bfloat162float(h1);
                ol[q] = pk2(r0, r1);
                ((bf162*)&oh[q])->x = h0; ((bf162*)&oh[q])->y = h1;
            }
            *(uint4*)(sm + CWK(0) + (j * CST + seg * 8) * 2) = *(uint4*)oh;
            *(uint4*)(sm + CWK(1) + (j * CST + seg * 8) * 2) = *(uint4*)ol;
            *(uint4*)(sm + CV(0) + (j * CST + seg * 8) * 2) = *(const uint4*)(Vh + seg * 8);
            *(uint4*)(sm + CV(1) + (j * CST + seg * 8) * 2) = *(const uint4*)(Vl + seg * 8);
        }
    }
    __syncthreads();

    float acc[8][4];
#pragma unroll
    for (int ni = 0; ni < 8; ni++)
#pragma unroll
        for (int q = 0; q < 4; q++) acc[ni][q] = 0.f;

#pragma unroll
    for (int ks = 0; ks < 8; ks++) {
        // A = wK^T: trans load, rows j (k-dim), cols dk (m-dim)
        uint32_t ah[4], al[4];
        {
            int row = ks * 16 + (l & 7) + ((l >> 4) & 1) * 8;
            int col = 16 * wid + ((l >> 3) & 1) * 8;
            ldsm4t(ah, sb + CWK(0) + (row * CST + col) * 2);
            ldsm4t(al, sb + CWK(1) + (row * CST + col) * 2);
        }
        uint32_t bv[2][8][2];
#pragma unroll
        for (int p = 0; p < 2; p++)
#pragma unroll
            for (int na = 0; na < 4; na++) {
                int row = ks * 16 + ((l >> 3) & 1) * 8 + (l & 7);
                int col = na * 16 + (l >> 4) * 8;
                uint32_t r4[4];
                ldsm4t(r4, sb + CV(p) + (row * CST + col) * 2);
                bv[p][na * 2][0] = r4[0]; bv[p][na * 2][1] = r4[1];
                bv[p][na * 2 + 1][0] = r4[2]; bv[p][na * 2 + 1][1] = r4[3];
            }
#pragma unroll
        for (int ni = 0; ni < 8; ni++) mma_bf(acc[ni], ah, bv[0][ni]);
#pragma unroll
        for (int ni = 0; ni < 8; ni++) mma_bf(acc[ni], ah, bv[1][ni]);
#pragma unroll
        for (int ni = 0; ni < 8; ni++) mma_bf(acc[ni], al, bv[0][ni]);
    }

    // write U (fp32)
    float* U = g_U + ((size_t)bh * NCHUNK + ci) * HD * HD;
    const int g = l >> 2, tq = l & 3;
#pragma unroll
    for (int ni = 0; ni < 8; ni++) {
        int col = ni * 8 + 2 * tq;
        int row1 = 16 * wid + g, row2 = row1 + 8;
        *(float2*)(U + row1 * HD + col) = make_float2(acc[ni][0], acc[ni][1]);
        *(float2*)(U + row2 * HD + col) = make_float2(acc[ni][2], acc[ni][3]);
    }
}

// ---------------------------------------------------------------------------
// Phase B: prefix scan over chunks: state_{c+1} = gamma^128 * state_c + U_c.
// Emits split-bf16 state per chunk. One block per bh.
// ---------------------------------------------------------------------------
__global__ __launch_bounds__(256) void state_scan_kernel() {
    const int bh = blockIdx.x, h = bh & (NH - 1);
    const float lg = lg2gamma(h);
    const float g128 = exp2f(lg * 128.0f);
    const int tid = threadIdx.x;

    float st[16];
#pragma unroll
    for (int k = 0; k < 16; k++) st[k] = 0.f;

    for (int c = 0; c < NCHUNK; c++) {
        const size_t off = ((size_t)bh * NCHUNK + c) * HD * HD;
#pragma unroll
        for (int k = 0; k < 16; k++) {
            int idx = tid + 256 * k;
            bf16 hv = __float2bfloat16(st[k]);
            g_Sth[off + idx] = hv;
            g_Stl[off + idx] = __float2bfloat16(st[k] - __bfloat162float(hv));
            st[k] = g128 * st[k] + g_U[off + idx];
        }
    }
}

// ---------------------------------------------------------------------------
// Phase C: per 128-row chunk: intra-chunk quadratic part (2 s-blocks) +
// cross-chunk term via state:  O_i += 0.125*gamma^(i-cstart+1) * Q_i @ state.
// ---------------------------------------------------------------------------
#define RST 72
#define RQ(p)  ((p)*18432)
#define RK(p)  (36864 + (p)*9216)
#define RV(p)  (55296 + (p)*9216)
#define RDW    73728
#define RET_SMEM 74752

__global__ __launch_bounds__(256) void retention_chunk_kernel() {
    extern __shared__ __align__(16) char sm[];
    float* dw = (float*)(sm + RDW);
    const int tid = threadIdx.x, l = tid & 31, wid = tid >> 5;
    const int bh = blockIdx.y, h = bh & (NH - 1);
    const int ci = blockIdx.x;
    const int t0 = ci * 128;
    const float lg = lg2gamma(h);
    const uint32_t sb = smaddr(sm);
    const size_t base = (size_t)bh * NT * HD;

    // load Q tile 128x64 (both parts)
#pragma unroll
    for (int p = 0; p < 2; p++) {
        const bf16* Qp = (p ? g_Ql : g_Qh) + base + (size_t)t0 * HD;
#pragma unroll
        for (int i = 0; i < 4; i++) {
            int flat = tid + 256 * i;
            int row = flat >> 3, seg = flat & 7;
            uint4 v = *(const uint4*)(Qp + (size_t)row * HD + seg * 8);
            *(uint4*)(sm + RQ(p) + (row * RST + seg * 8) * 2) = v;
        }
    }
    __syncthreads();

    uint32_t aq[2][4][4];
#pragma unroll
    for (int p = 0; p < 2; p++)
#pragma unroll
        for (int kc = 0; kc < 4; kc++) {
            int row = wid * 16 + (l & 7) + ((l >> 3) & 1) * 8;
            int col = kc * 16 + (l >> 4) * 8;
            ldsm4(aq[p][kc], sb + RQ(p) + (row * RST + col) * 2);
        }

    float oacc[8][4];
#pragma unroll
    for (int ni = 0; ni < 8; ni++)
#pragma unroll
        for (int q = 0; q < 4; q++) oacc[ni][q] = 0.f;

    const int g = l >> 2, tq = l & 3;
    const int il = 16 * wid + g;     // local row in [0,128)

    for (int s0 = t0; s0 <= t0 + 64; s0 += 64) {
        __syncthreads();
#pragma unroll
        for (int p = 0; p < 2; p++) {
            const bf16* Kp = (p ? g_Kl : g_Kh) + base + (size_t)s0 * HD;
            const bf16* Vp = (p ? g_Vl : g_Vh) + base + (size_t)s0 * HD;
#pragma unroll
            for (int i = 0; i < 2; i++) {
                int flat = tid + 256 * i;
                int row = flat >> 3, seg = flat & 7;
                uint4 kv = *(const uint4*)(Kp + (size_t)row * HD + seg * 8);
                *(uint4*)(sm + RK(p) + (row * RST + seg * 8) * 2) = kv;
                uint4 vv = *(const uint4*)(Vp + (size_t)row * HD + seg * 8);
                *(uint4*)(sm + RV(p) + (row * RST + seg * 8) * 2) = vv;
            }
        }
        if (tid < 192) {
            int diff = t0 - s0 - 63 + tid;
            dw[tid] = (diff >= 0) ? 0.125f * exp2f(lg * (float)diff) : 0.f;
        }
        __syncthreads();

        float sacc[8][4];
#pragma unroll
        for (int ni = 0; ni < 8; ni++)
#pragma unroll
            for (int q = 0; q < 4; q++) sacc[ni][q] = 0.f;
#pragma unroll
        for (int kc = 0; kc < 4; kc++) {
            uint32_t bk[2][8][2];
#pragma unroll
            for (int p = 0; p < 2; p++)
#pragma unroll
                for (int na = 0; na < 4; na++) {
                    int row = na * 16 + (l >> 4) * 8 + (l & 7);
                    int col = kc * 16 + ((l >> 3) & 1) * 8;
                    uint32_t r4[4];
                    ldsm4(r4, sb + RK(p) + (row * RST + col) * 2);
                    bk[p][na * 2][0] = r4[0]; bk[p][na * 2][1] = r4[1];
                    bk[p][na * 2 + 1][0] = r4[2]; bk[p][na * 2 + 1][1] = r4[3];
                }
#pragma unroll
            for (int ni = 0; ni < 8; ni++) mma_bf(sacc[ni], aq[0][kc], bk[0][ni]);
#pragma unroll
            for (int ni = 0; ni < 8; ni++) mma_bf(sacc[ni], aq[0][kc], bk[1][ni]);
#pragma unroll
            for (int ni = 0; ni < 8; ni++) mma_bf(sacc[ni], aq[1][kc], bk[0][ni]);
        }

#pragma unroll
        for (int ni = 0; ni < 8; ni++) {
            int jb = ni * 8 + 2 * tq;
            sacc[ni][0] *= dw[63 + il - jb];
            sacc[ni][1] *= dw[63 + il - (jb + 1)];
            sacc[ni][2] *= dw[63 + il + 8 - jb];
            sacc[ni][3] *= dw[63 + il + 8 - (jb + 1)];
        }

        uint32_t ash[4][4], asl[4][4];
#pragma unroll
        for (int kc = 0; kc < 4; kc++) {
            const float* e0 = sacc[2 * kc];
            const float* e1 = sacc[2 * kc + 1];
            float src[8] = {e0[0], e0[1], e0[2], e0[3], e1[0], e1[1], e1[2], e1[3]};
            float hv[8], lv[8];
#pragma unroll
            for (int q = 0; q < 8; q++) {
                bf16 hb = __float2bfloat16(src[q]);
                hv[q] = __bfloat162float(hb);
                lv[q] = src[q] - hv[q];
            }
            ash[kc][0] = pk2(hv[0], hv[1]); ash[kc][1] = pk2(hv[2], hv[3]);
            ash[kc][2] = pk2(hv[4], hv[5]); ash[kc][3] = pk2(hv[6], hv[7]);
            asl[kc][0] = pk2(lv[0], lv[1]); asl[kc][1] = pk2(lv[2], lv[3]);
            asl[kc][2] = pk2(lv[4], lv[5]); asl[kc][3] = pk2(lv[6], lv[7]);
        }

#pragma unroll
        for (int kc = 0; kc < 4; kc++) {
            uint32_t bv[2][8][2];
#pragma unroll
            for (int p = 0; p < 2; p++)
#pragma unroll
                for (int na = 0; na < 4; na++) {
                    int row = kc * 16 + ((l >> 3) & 1) * 8 + (l & 7);
                    int col = na * 16 + (l >> 4) * 8;
                    uint32_t r4[4];
                    ldsm4t(r4, sb + RV(p) + (row * RST + col) * 2);
                    bv[p][na * 2][0] = r4[0]; bv[p][na * 2][1] = r4[1];
                    bv[p][na * 2 + 1][0] = r4[2]; bv[p][na * 2 + 1][1] = r4[3];
                }
#pragma unroll
            for (int ni = 0; ni < 8; ni++) mma_bf(oacc[ni], ash[kc], bv[0][ni]);
#pragma unroll
            for (int ni = 0; ni < 8; ni++) mma_bf(oacc[ni], ash[kc], bv[1][ni]);
#pragma unroll
            for (int ni = 0; ni < 8; ni++) mma_bf(oacc[ni], asl[kc], bv[0][ni]);
        }
    }

    // -------- cross-chunk term: O_i += 0.125*gamma^(il+1) * Q_i @ state --------
    __syncthreads();
    {
        const size_t soff = ((size_t)bh * NCHUNK + ci) * HD * HD;
#pragma unroll
        for (int i2 = 0; i2 < 4; i2++) {
            int job = tid + 256 * i2;           // 1024 jobs = 2 parts x 64 rows x 8 segs
            int p = job >> 9;
            int row = (job >> 3) & 63;
            int seg = job & 7;
            const bf16* src = (p ? g_Stl : g_Sth) + soff + row * HD + seg * 8;
            *(uint4*)(sm + RK(p) + (row * RST + seg * 8) * 2) = *(const uint4*)src;
        }
    }
    __syncthreads();

    float cacc[8][4];
#pragma unroll
    for (int ni = 0; ni < 8; ni++)
#pragma unroll
        for (int q = 0; q < 4; q++) cacc[ni][q] = 0.f;
#pragma unroll
    for (int kc = 0; kc < 4; kc++) {
        uint32_t bs[2][8][2];
#pragma unroll
        for (int p = 0; p < 2; p++)
#pragma unroll
            for (int na = 0; na < 4; na++) {
                int row = kc * 16 + ((l >> 3) & 1) * 8 + (l & 7);
                int col = na * 16 + (l >> 4) * 8;
                uint32_t r4[4];
                ldsm4t(r4, sb + RK(p) + (row * RST + col) * 2);
                bs[p][na * 2][0] = r4[0]; bs[p][na * 2][1] = r4[1];
                bs[p][na * 2 + 1][0] = r4[2]; bs[p][na * 2 + 1][1] = r4[3];
            }
#pragma unroll
        for (int ni = 0; ni < 8; ni++) mma_bf(cacc[ni], aq[0][kc], bs[0][ni]);
#pragma unroll
        for (int ni = 0; ni < 8; ni++) mma_bf(cacc[ni], aq[0][kc], bs[1][ni]);
#pragma unroll
        for (int ni = 0; ni < 8; ni++) mma_bf(cacc[ni], aq[1][kc], bs[0][ni]);
    }
    {
        const float w1 = 0.125f * exp2f(lg * (float)(il + 1));
        const float w2 = 0.125f * exp2f(lg * (float)(il + 9));
#pragma unroll
        for (int ni = 0; ni < 8; ni++) {
            oacc[ni][0] += w1 * cacc[ni][0];
            oacc[ni][1] += w1 * cacc[ni][1];
            oacc[ni][2] += w2 * cacc[ni][2];
            oacc[ni][3] += w2 * cacc[ni][3];
        }
    }

    // write O (fp32)
#pragma unroll
    for (int ni = 0; ni < 8; ni++) {
        int col = ni * 8 + 2 * tq;
        int r1 = t0 + il, r2 = r1 + 8;
        *(float2*)(g_O + (base + (size_t)r1 * HD + col)) = make_float2(oacc[ni][0], oacc[ni][1]);
        *(float2*)(g_O + (base + (size_t)r2 * HD + col)) = make_float2(oacc[ni][2], oacc[ni][3]);
    }
}

// ---------------------------------------------------------------------------
// GroupNorm over (D,T) per (b,h); writes split bf16 into (B,T,C).
// ---------------------------------------------------------------------------
__global__ __launch_bounds__(256) void groupnorm_kernel(const float* __restrict__ gnw,
                                                        const float* __restrict__ gnb) {
    const int bh = blockIdx.x;
    const int b = bh >> 4, h = bh & 15;
    const float* bsrc = g_O + (size_t)bh * (NT * HD);
    const int tid = threadIdx.x;

    double s1 = 0.0, s2 = 0.0;
    for (int i = tid; i < NT * HD; i += 256) {
        float v = bsrc[i];
        s1 += v;
        s2 += (double)v * v;
    }
    __shared__ double r1[256], r2[256];
    r1[tid] = s1; r2[tid] = s2;
    __syncthreads();
    for (int s = 128; s > 0; s >>= 1) {
        if (tid < s) { r1[tid] += r1[tid + s]; r2[tid] += r2[tid + s]; }
        __syncthreads();
    }
    __shared__ float smu, srs;
    if (tid == 0) {
        double mu  = r1[0] / (double)(NT * HD);
        double var = r2[0] / (double)(NT * HD) - mu * mu;
        smu = (float)mu;
        srs = (float)(1.0 / sqrt(var + 1e-5));
    }
    __syncthreads();
    float mu = smu, rs = srs;
    for (int i = tid; i < NT * HD; i += 256) {
        int t = i >> 6, d = i & 63;
        int c = h * 64 + d;
        float v = (bsrc[i] - mu) * rs * gnw[c] + gnb[c];
        size_t idx = ((size_t)b * NT + t) * NC + c;
        bf16 hv = __float2bfloat16(v);
        g_Ynh[idx] = hv;
        g_Ynl[idx] = __float2bfloat16(v - __bfloat162float(hv));
    }
}

// ---------------------------------------------------------------------------
// Launch. Order chosen so launch #6 (ncu -s 5 -c 1) = gemm_mma<0> (QKV GEMM).
// ---------------------------------------------------------------------------
extern "C" void kernel_launch(void* const* d_in, const int* in_sizes, int n_in,
                              void* d_out, int out_size) {
    const float* x   = (const float*)d_in[0];
    const float* Wq  = (const float*)d_in[1];
    const float* Wk  = (const float*)d_in[2];
    const float* Wv  = (const float*)d_in[3];
    const float* Wo  = (const float*)d_in[4];
    const float* gnw = (const float*)d_in[5];
    const float* gnb = (const float*)d_in[6];
    float* out = (float*)d_out;

    cudaFuncSetAttribute(gemm_mma<0>, cudaFuncAttributeMaxDynamicSharedMemorySize, GEMM_SMEM);
    cudaFuncSetAttribute(gemm_mma<1>, cudaFuncAttributeMaxDynamicSharedMemorySize, GEMM_SMEM);
    cudaFuncSetAttribute(chunk_state_kernel, cudaFuncAttributeMaxDynamicSharedMemorySize, CHUNK_SMEM);
    cudaFuncSetAttribute(retention_chunk_kernel, cudaFuncAttributeMaxDynamicSharedMemorySize, RET_SMEM);

    split_x_kernel<<<1024, 256>>>(x);                                   // 1
    split_w_kernel<<<512, 256>>>(Wq, 0);                                // 2
    split_w_kernel<<<512, 256>>>(Wk, 1);                                // 3
    split_w_kernel<<<512, 256>>>(Wv, 2);                                // 4
    split_w_kernel<<<512, 256>>>(Wo, 3);                                // 5
    gemm_mma<0><<<dim3(MTOT / 128, NC / 128, 3), 256, GEMM_SMEM>>>(nullptr);  // 6 (profiled)
    chunk_state_kernel<<<dim3(NCHUNK, NB * NH), 128, CHUNK_SMEM>>>();   // 7
    state_scan_kernel<<<NB * NH, 256>>>();                              // 8
    retention_chunk_kernel<<<dim3(NCHUNK, NB * NH), 256, RET_SMEM>>>(); // 9
    groupnorm_kernel<<<NB * NH, 256>>>(gnw, gnb);                       // 10
    gemm_mma<1><<<dim3(MTOT / 128, NC / 128, 1), 256, GEMM_SMEM>>>(out);// 11
}

// round 6
// speedup vs baseline: 2.4307x; 1.0031x over previous
#include <cuda_runtime.h>
#include <cuda_bf16.h>
#include <math.h>
#include <cstdint>

#define NB 2
#define NT 2048
#define NH 16
#define HD 64
#define NC 1024
#define MTOT (NB*NT)   // 4096
#define NCHUNK 16      // T / 128

typedef __nv_bfloat16  bf16;
typedef __nv_bfloat162 bf162;

// ---------------------------------------------------------------------------
// Scratch (allocation-free rule: __device__ globals)
// ---------------------------------------------------------------------------
__device__ __align__(16) bf16 g_Xh[MTOT*NC],  g_Xl[MTOT*NC];
__device__ __align__(16) bf16 g_Wh[4*NC*NC],  g_Wl[4*NC*NC];
__device__ __align__(16) bf16 g_Qh[NB*NH*NT*HD], g_Ql[NB*NH*NT*HD];
__device__ __align__(16) bf16 g_Kh[NB*NH*NT*HD], g_Kl[NB*NH*NT*HD];
__device__ __align__(16) bf16 g_Vh[NB*NH*NT*HD], g_Vl[NB*NH*NT*HD];
__device__ __align__(16) float g_O[NB*NH*NT*HD];
__device__ __align__(16) bf16 g_Ynh[MTOT*NC], g_Ynl[MTOT*NC];
__device__ __align__(16) float g_U[NB*NH*NCHUNK*HD*HD];
__device__ __align__(16) bf16 g_Sth[NB*NH*NCHUNK*HD*HD];
__device__ __align__(16) bf16 g_Stl[NB*NH*NCHUNK*HD*HD];

// ---------------------------------------------------------------------------
// Helpers
// ---------------------------------------------------------------------------
__device__ __forceinline__ uint32_t smaddr(const void* p) {
    uint32_t a;
    asm("{ .reg .u64 t; cvta.to.shared.u64 t, %1; cvt.u32.u64 %0, t; }"
        : "=r"(a) : "l"(p));
    return a;
}
__device__ __forceinline__ void ldsm4(uint32_t r[4], uint32_t a) {
    asm volatile("ldmatrix.sync.aligned.m8n8.x4.shared.b16 {%0,%1,%2,%3}, [%4];"
        : "=r"(r[0]), "=r"(r[1]), "=r"(r[2]), "=r"(r[3]) : "r"(a));
}
__device__ __forceinline__ void ldsm4t(uint32_t r[4], uint32_t a) {
    asm volatile("ldmatrix.sync.aligned.m8n8.x4.trans.shared.b16 {%0,%1,%2,%3}, [%4];"
        : "=r"(r[0]), "=r"(r[1]), "=r"(r[2]), "=r"(r[3]) : "r"(a));
}
__device__ __forceinline__ void mma_bf(float c[4], const uint32_t a[4], const uint32_t b[2]) {
    asm volatile(
        "mma.sync.aligned.m16n8k16.row.col.f32.bf16.bf16.f32 "
        "{%0,%1,%2,%3}, {%4,%5,%6,%7}, {%8,%9}, {%0,%1,%2,%3};"
        : "+f"(c[0]), "+f"(c[1]), "+f"(c[2]), "+f"(c[3])
        : "r"(a[0]), "r"(a[1]), "r"(a[2]), "r"(a[3]), "r"(b[0]), "r"(b[1]));
}
__device__ __forceinline__ uint32_t pk2(float a, float b) {
    bf162 t = __floats2bfloat162_rn(a, b);
    return *reinterpret_cast<uint32_t*>(&t);
}
__device__ __forceinline__ float lg2gamma(int h) {
    double gamma = 1.0 - exp2(-5.0 - 0.5 * (double)h);
    return (float)log2(gamma);
}
__device__ __forceinline__ void cpa16(uint32_t s, const void* g) {
    asm volatile("cp.async.cg.shared.global [%0], [%1], 16;" :: "r"(s), "l"(g));
}
#define CP_COMMIT() asm volatile("cp.async.commit_group;" ::: "memory")
#define CP_WAIT0()  asm volatile("cp.async.wait_group 0;" ::: "memory")

// split a float4 into hi/lo bf162 pairs
__device__ __forceinline__ void split4(float4 v, uint2& hi, uint2& lo) {
    bf162 h0 = __floats2bfloat162_rn(v.x, v.y);
    bf162 h1 = __floats2bfloat162_rn(v.z, v.w);
    bf162 l0 = __floats2bfloat162_rn(v.x - __bfloat162float(h0.x),
                                     v.y - __bfloat162float(h0.y));
    bf162 l1 = __floats2bfloat162_rn(v.z - __bfloat162float(h1.x),
                                     v.w - __bfloat162float(h1.y));
    hi.x = *(uint32_t*)&h0; hi.y = *(uint32_t*)&h1;
    lo.x = *(uint32_t*)&l0; lo.y = *(uint32_t*)&l1;
}

// ---------------------------------------------------------------------------
// Splits (vectorized)
// ---------------------------------------------------------------------------
__global__ __launch_bounds__(256) void split_x_kernel(const float4* __restrict__ src) {
    int i = blockIdx.x * blockDim.x + threadIdx.x;
    if (i >= MTOT * NC / 4) return;
    uint2 hi, lo;
    split4(src[i], hi, lo);
    *(uint2*)(g_Xh + 4 * (size_t)i) = hi;
    *(uint2*)(g_Xl + 4 * (size_t)i) = lo;
}
__global__ __launch_bounds__(256) void split_w2_kernel(const float4* __restrict__ a,
                                                       const float4* __restrict__ b,
                                                       int wa, int wb) {
    const int n = NC * NC / 4;
    int i = blockIdx.x * blockDim.x + threadIdx.x;
    if (i >= 2 * n) return;
    const float4* src = (i < n) ? a : b;
    int widx = (i < n) ? wa : wb;
    int j = (i < n) ? i : i - n;
    uint2 hi, lo;
    split4(src[j], hi, lo);
    *(uint2*)(g_Wh + (size_t)widx * NC * NC + 4 * (size_t)j) = hi;
    *(uint2*)(g_Wl + (size_t)widx * NC * NC + 4 * (size_t)j) = lo;
}

// ---------------------------------------------------------------------------
// bf16x3 GEMM with cp.async 2-stage pipeline.
// C[r,n] = sum_k A[r,k]*W[n,k]; block 128x128, 8 warps, warp tile 32x64.
// ---------------------------------------------------------------------------
#define AST 40
#define KCH 32
#define SOA(buf,p) ((buf)*20480 + (p)*10240)
#define SOB(buf,p) (40960 + (buf)*20480 + (p)*10240)
#define GEMM_SMEM 81920

template<int MODE>
__global__ __launch_bounds__(256) void gemm_mma(float* __restrict__ Cf) {
    extern __shared__ __align__(16) char sm[];
    const int tid = threadIdx.x, l = tid & 31, wid = tid >> 5;
    const int wm = wid & 3, wn = wid >> 2;
    const int r0 = blockIdx.x * 128, n0 = blockIdx.y * 128;
    const int z = blockIdx.z;
    const int wsel = (MODE == 0) ? z : 3;

    const bf16* Ah = (MODE == 0) ? g_Xh : g_Ynh;
    const bf16* Al = (MODE == 0) ? g_Xl : g_Ynl;
    const bf16* Wh = g_Wh + (size_t)wsel * NC * NC;
    const bf16* Wl = g_Wl + (size_t)wsel * NC * NC;
    const uint32_t sb = smaddr(sm);

    float acc[2][8][4];
#pragma unroll
    for (int mi = 0; mi < 2; mi++)
#pragma unroll
        for (int ni = 0; ni < 8; ni++)
#pragma unroll
            for (int q = 0; q < 4; q++) acc[mi][ni][q] = 0.f;

    // async-load one k-chunk (32 cols) into buffer `buf`
    auto load_chunk = [&](int kb, int buf) {
#pragma unroll
        for (int i = 0; i < 8; i++) {
            int j = tid + 256 * i;
            int row = (j >> 2) & 127, seg = j & 3, part = (j >> 9) & 1;
            if (j < 1024) {
                const bf16* src = (part ? Al : Ah) + (size_t)(r0 + row) * NC + kb + seg * 8;
                cpa16(sb + SOA(buf, part) + (row * AST + seg * 8) * 2, src);
            } else {
                const bf16* src = (part ? Wl : Wh) + (size_t)(n0 + row) * NC + kb + seg * 8;
                cpa16(sb + SOB(buf, part) + (row * AST + seg * 8) * 2, src);
            }
        }
    };

    load_chunk(0, 0);
    CP_COMMIT();

    for (int c = 0; c < KCH; c++) {
        const int buf = c & 1;
        CP_WAIT0();
        __syncthreads();                 // chunk c resident; all warps done reading buf^1
        if (c + 1 < KCH) {
            load_chunk((c + 1) * 32, buf ^ 1);
            CP_COMMIT();
        }
#pragma unroll
        for (int ks = 0; ks < 32; ks += 16) {
            uint32_t af[2][2][4];
#pragma unroll
            for (int p = 0; p < 2; p++)
#pragma unroll
                for (int mi = 0; mi < 2; mi++) {
                    int row = wm * 32 + mi * 16 + (l & 7) + ((l >> 3) & 1) * 8;
                    int col = ks + (l >> 4) * 8;
                    ldsm4(af[p][mi], sb + SOA(buf, p) + (row * AST + col) * 2);
                }
            uint32_t bfr[2][8][2];
#pragma unroll
            for (int p = 0; p < 2; p++)
#pragma unroll
                for (int na = 0; na < 4; na++) {
                    int row = wn * 64 + na * 16 + (l >> 4) * 8 + (l & 7);
                    int col = ks + ((l >> 3) & 1) * 8;
                    uint32_t r4[4];
                    ldsm4(r4, sb + SOB(buf, p) + (row * AST + col) * 2);
                    bfr[p][na * 2][0] = r4[0]; bfr[p][na * 2][1] = r4[1];
                    bfr[p][na * 2 + 1][0] = r4[2]; bfr[p][na * 2 + 1][1] = r4[3];
                }
#pragma unroll
            for (int mi = 0; mi < 2; mi++)
#pragma unroll
                for (int ni = 0; ni < 8; ni++) mma_bf(acc[mi][ni], af[0][mi], bfr[0][ni]);
#pragma unroll
            for (int mi = 0; mi < 2; mi++)
#pragma unroll
                for (int ni = 0; ni < 8; ni++) mma_bf(acc[mi][ni], af[0][mi], bfr[1][ni]);
#pragma unroll
            for (int mi = 0; mi < 2; mi++)
#pragma unroll
                for (int ni = 0; ni < 8; ni++) mma_bf(acc[mi][ni], af[1][mi], bfr[0][ni]);
        }
    }

    const int g = l >> 2, tq = l & 3;
    bf16* oh = nullptr; bf16* ol = nullptr;
    if (MODE == 0) {
        oh = (z == 0) ? g_Qh : (z == 1) ? g_Kh : g_Vh;
        ol = (z == 0) ? g_Ql : (z == 1) ? g_Kl : g_Vl;
    }
#pragma unroll
    for (int mi = 0; mi < 2; mi++)
#pragma unroll
        for (int ni = 0; ni < 8; ni++) {
            int rbase = r0 + wm * 32 + mi * 16 + g;
            int n = n0 + wn * 64 + ni * 8 + 2 * tq;
#pragma unroll
            for (int rr = 0; rr < 2; rr++) {
                int row = rbase + rr * 8;
                float v0 = acc[mi][ni][rr * 2 + 0];
                float v1 = acc[mi][ni][rr * 2 + 1];
                if (MODE == 0) {
                    int b = row >> 11, t = row & (NT - 1);
                    int hh = n >> 6, d = n & 63;
                    size_t idx = (((size_t)b * NH + hh) * NT + t) * HD + d;
                    bf16 h0 = __float2bfloat16(v0);
                    bf16 h1 = __float2bfloat16(v1);
                    bf162 hv; hv.x = h0; hv.y = h1;
                    bf162 lv;
                    lv.x = __float2bfloat16(v0 - __bfloat162float(h0));
                    lv.y = __float2bfloat16(v1 - __bfloat162float(h1));
                    *(bf162*)(oh + idx) = hv;
                    *(bf162*)(ol + idx) = lv;
                } else {
                    *(float2*)(Cf + (size_t)row * NC + n) = make_float2(v0, v1);
                }
            }
        }
}

// ---------------------------------------------------------------------------
// Phase A: per-chunk KV summary  U_c[dk][dv] = sum_j gamma^(cend-j) k_j[dk] v_j[dv]
// ---------------------------------------------------------------------------
#define CST 72
#define CWK(p) ((p)*18432)
#define CV(p)  (36864 + (p)*18432)
#define CHUNK_SMEM 73728

__global__ __launch_bounds__(128) void chunk_state_kernel() {
    extern __shared__ __align__(16) char sm[];
    const int tid = threadIdx.x, l = tid & 31, wid = tid >> 5;
    const int ci = blockIdx.x, bh = blockIdx.y, h = bh & (NH - 1);
    const float lg = lg2gamma(h);
    const uint32_t sb = smaddr(sm);
    const size_t base = (size_t)bh * NT * HD + (size_t)ci * 128 * HD;

    {
        const int j = tid;
        const float w = exp2f(lg * (float)(127 - j));
        const bf16* Kh = g_Kh + base + (size_t)j * HD;
        const bf16* Kl = g_Kl + base + (size_t)j * HD;
        const bf16* Vh = g_Vh + base + (size_t)j * HD;
        const bf16* Vl = g_Vl + base + (size_t)j * HD;
#pragma unroll
        for (int seg = 0; seg < 8; seg++) {
            uint4 khv = *(const uint4*)(Kh + seg * 8);
            uint4 klv = *(const uint4*)(Kl + seg * 8);
            const bf162* kh2 = (const bf162*)&khv;
            const bf162* kl2 = (const bf162*)&klv;
            uint32_t oh[4], ol[4];
#pragma unroll
            for (int q = 0; q < 4; q++) {
                float f0 = __bfloat162float(kh2[q].x) + __bfloat162float(kl2[q].x);
                float f1 = __bfloat162float(kh2[q].y) + __bfloat162float(kl2[q].y);
                f0 *= w; f1 *= w;
                bf16 h0 = __float2bfloat16(f0), h1 = __float2bfloat16(f1);
                float r0 = f0 - __bfloat162float(h0);
                float r1 = f1 - __bfloat162float(h1);
                ol[q] = pk2(r0, r1);
                bf162 hv; hv.x = h0; hv.y = h1;
                oh[q] = *(uint32_t*)&hv;
            }
            *(uint4*)(sm + CWK(0) + (j * CST + seg * 8) * 2) = *(uint4*)oh;
            *(uint4*)(sm + CWK(1) + (j * CST + seg * 8) * 2) = *(uint4*)ol;
            *(uint4*)(sm + CV(0) + (j * CST + seg * 8) * 2) = *(const uint4*)(Vh + seg * 8);
            *(uint4*)(sm + CV(1) + (j * CST + seg * 8) * 2) = *(const uint4*)(Vl + seg * 8);
        }
    }
    __syncthreads();

    float acc[8][4];
#pragma unroll
    for (int ni = 0; ni < 8; ni++)
#pragma unroll
        for (int q = 0; q < 4; q++) acc[ni][q] = 0.f;

#pragma unroll
    for (int ks = 0; ks < 8; ks++) {
        uint32_t ah[4], al[4];
        {
            int row = ks * 16 + (l & 7) + ((l >> 4) & 1) * 8;
            int col = 16 * wid + ((l >> 3) & 1) * 8;
            ldsm4t(ah, sb + CWK(0) + (row * CST + col) * 2);
            ldsm4t(al, sb + CWK(1) + (row * CST + col) * 2);
        }
        uint32_t bv[2][8][2];
#pragma unroll
        for (int p = 0; p < 2; p++)
#pragma unroll
            for (int na = 0; na < 4; na++) {
                int row = ks * 16 + ((l >> 3) & 1) * 8 + (l & 7);
                int col = na * 16 + (l >> 4) * 8;
                uint32_t r4[4];
                ldsm4t(r4, sb + CV(p) + (row * CST + col) * 2);
                bv[p][na * 2][0] = r4[0]; bv[p][na * 2][1] = r4[1];
                bv[p][na * 2 + 1][0] = r4[2]; bv[p][na * 2 + 1][1] = r4[3];
            }
#pragma unroll
        for (int ni = 0; ni < 8; ni++) mma_bf(acc[ni], ah, bv[0][ni]);
#pragma unroll
        for (int ni = 0; ni < 8; ni++) mma_bf(acc[ni], ah, bv[1][ni]);
#pragma unroll
        for (int ni = 0; ni < 8; ni++) mma_bf(acc[ni], al, bv[0][ni]);
    }

    float* U = g_U + ((size_t)bh * NCHUNK + ci) * HD * HD;
    const int g = l >> 2, tq = l & 3;
#pragma unroll
    for (int ni = 0; ni < 8; ni++) {
        int col = ni * 8 + 2 * tq;
        int row1 = 16 * wid + g, row2 = row1 + 8;
        *(float2*)(U + row1 * HD + col) = make_float2(acc[ni][0], acc[ni][1]);
        *(float2*)(U + row2 * HD + col) = make_float2(acc[ni][2], acc[ni][3]);
    }
}

// ---------------------------------------------------------------------------
// Phase B: prefix scan over chunks.
// ---------------------------------------------------------------------------
__global__ __launch_bounds__(256) void state_scan_kernel() {
    const int bh = blockIdx.x, h = bh & (NH - 1);
    const float lg = lg2gamma(h);
    const float g128 = exp2f(lg * 128.0f);
    const int tid = threadIdx.x;

    float st[16];
#pragma unroll
    for (int k = 0; k < 16; k++) st[k] = 0.f;

    for (int c = 0; c < NCHUNK; c++) {
        const size_t off = ((size_t)bh * NCHUNK + c) * HD * HD;
#pragma unroll
        for (int k = 0; k < 16; k++) {
            int idx = tid + 256 * k;
            bf16 hv = __float2bfloat16(st[k]);
            g_Sth[off + idx] = hv;
            g_Stl[off + idx] = __float2bfloat16(st[k] - __bfloat162float(hv));
            st[k] = g128 * st[k] + g_U[off + idx];
        }
    }
}

// ---------------------------------------------------------------------------
// Phase C: intra-chunk quadratic + cross-chunk state term.
// ---------------------------------------------------------------------------
#define RST 72
#define RQ(p)  ((p)*18432)
#define RK(p)  (36864 + (p)*9216)
#define RV(p)  (55296 + (p)*9216)
#define RDW    73728
#define RET_SMEM 74752

__global__ __launch_bounds__(256) void retention_chunk_kernel() {
    extern __shared__ __align__(16) char sm[];
    float* dw = (float*)(sm + RDW);
    const int tid = threadIdx.x, l = tid & 31, wid = tid >> 5;
    const int bh = blockIdx.y, h = bh & (NH - 1);
    const int ci = blockIdx.x;
    const int t0 = ci * 128;
    const float lg = lg2gamma(h);
    const uint32_t sb = smaddr(sm);
    const size_t base = (size_t)bh * NT * HD;

#pragma unroll
    for (int p = 0; p < 2; p++) {
        const bf16* Qp = (p ? g_Ql : g_Qh) + base + (size_t)t0 * HD;
#pragma unroll
        for (int i = 0; i < 4; i++) {
            int flat = tid + 256 * i;
            int row = flat >> 3, seg = flat & 7;
            uint4 v = *(const uint4*)(Qp + (size_t)row * HD + seg * 8);
            *(uint4*)(sm + RQ(p) + (row * RST + seg * 8) * 2) = v;
        }
    }
    __syncthreads();

    uint32_t aq[2][4][4];
#pragma unroll
    for (int p = 0; p < 2; p++)
#pragma unroll
        for (int kc = 0; kc < 4; kc++) {
            int row = wid * 16 + (l & 7) + ((l >> 3) & 1) * 8;
            int col = kc * 16 + (l >> 4) * 8;
            ldsm4(aq[p][kc], sb + RQ(p) + (row * RST + col) * 2);
        }

    float oacc[8][4];
#pragma unroll
    for (int ni = 0; ni < 8; ni++)
#pragma unroll
        for (int q = 0; q < 4; q++) oacc[ni][q] = 0.f;

    const int g = l >> 2, tq = l & 3;
    const int il = 16 * wid + g;

    for (int s0 = t0; s0 <= t0 + 64; s0 += 64) {
        __syncthreads();
#pragma unroll
        for (int p = 0; p < 2; p++) {
            const bf16* Kp = (p ? g_Kl : g_Kh) + base + (size_t)s0 * HD;
            const bf16* Vp = (p ? g_Vl : g_Vh) + base + (size_t)s0 * HD;
#pragma unroll
            for (int i = 0; i < 2; i++) {
                int flat = tid + 256 * i;
                int row = flat >> 3, seg = flat & 7;
                uint4 kv = *(const uint4*)(Kp + (size_t)row * HD + seg * 8);
                *(uint4*)(sm + RK(p) + (row * RST + seg * 8) * 2) = kv;
                uint4 vv = *(const uint4*)(Vp + (size_t)row * HD + seg * 8);
                *(uint4*)(sm + RV(p) + (row * RST + seg * 8) * 2) = vv;
            }
        }
        if (tid < 192) {
            int diff = t0 - s0 - 63 + tid;
            dw[tid] = (diff >= 0) ? 0.125f * exp2f(lg * (float)diff) : 0.f;
        }
        __syncthreads();

        float sacc[8][4];
#pragma unroll
        for (int ni = 0; ni < 8; ni++)
#pragma unroll
            for (int q = 0; q < 4; q++) sacc[ni][q] = 0.f;
#pragma unroll
        for (int kc = 0; kc < 4; kc++) {
            uint32_t bk[2][8][2];
#pragma unroll
            for (int p = 0; p < 2; p++)
#pragma unroll
                for (int na = 0; na < 4; na++) {
                    int row = na * 16 + (l >> 4) * 8 + (l & 7);
                    int col = kc * 16 + ((l >> 3) & 1) * 8;
                    uint32_t r4[4];
                    ldsm4(r4, sb + RK(p) + (row * RST + col) * 2);
                    bk[p][na * 2][0] = r4[0]; bk[p][na * 2][1] = r4[1];
                    bk[p][na * 2 + 1][0] = r4[2]; bk[p][na * 2 + 1][1] = r4[3];
                }
#pragma unroll
            for (int ni = 0; ni < 8; ni++) mma_bf(sacc[ni], aq[0][kc], bk[0][ni]);
#pragma unroll
            for (int ni = 0; ni < 8; ni++) mma_bf(sacc[ni], aq[0][kc], bk[1][ni]);
#pragma unroll
            for (int ni = 0; ni < 8; ni++) mma_bf(sacc[ni], aq[1][kc], bk[0][ni]);
        }

#pragma unroll
        for (int ni = 0; ni < 8; ni++) {
            int jb = ni * 8 + 2 * tq;
            sacc[ni][0] *= dw[63 + il - jb];
            sacc[ni][1] *= dw[63 + il - (jb + 1)];
            sacc[ni][2] *= dw[63 + il + 8 - jb];
            sacc[ni][3] *= dw[63 + il + 8 - (jb + 1)];
        }

        uint32_t ash[4][4], asl[4][4];
#pragma unroll
        for (int kc = 0; kc < 4; kc++) {
            const float* e0 = sacc[2 * kc];
            const float* e1 = sacc[2 * kc + 1];
            float src[8] = {e0[0], e0[1], e0[2], e0[3], e1[0], e1[1], e1[2], e1[3]};
            float hv[8], lv[8];
#pragma unroll
            for (int q = 0; q < 8; q++) {
                bf16 hb = __float2bfloat16(src[q]);
                hv[q] = __bfloat162float(hb);
                lv[q] = src[q] - hv[q];
            }
            ash[kc][0] = pk2(hv[0], hv[1]); ash[kc][1] = pk2(hv[2], hv[3]);
            ash[kc][2] = pk2(hv[4], hv[5]); ash[kc][3] = pk2(hv[6], hv[7]);
            asl[kc][0] = pk2(lv[0], lv[1]); asl[kc][1] = pk2(lv[2], lv[3]);
            asl[kc][2] = pk2(lv[4], lv[5]); asl[kc][3] = pk2(lv[6], lv[7]);
        }

#pragma unroll
        for (int kc = 0; kc < 4; kc++) {
            uint32_t bv[2][8][2];
#pragma unroll
            for (int p = 0; p < 2; p++)
#pragma unroll
                for (int na = 0; na < 4; na++) {
                    int row = kc * 16 + ((l >> 3) & 1) * 8 + (l & 7);
                    int col = na * 16 + (l >> 4) * 8;
                    uint32_t r4[4];
                    ldsm4t(r4, sb + RV(p) + (row * RST + col) * 2);
                    bv[p][na * 2][0] = r4[0]; bv[p][na * 2][1] = r4[1];
                    bv[p][na * 2 + 1][0] = r4[2]; bv[p][na * 2 + 1][1] = r4[3];
                }
#pragma unroll
            for (int ni = 0; ni < 8; ni++) mma_bf(oacc[ni], ash[kc], bv[0][ni]);
#pragma unroll
            for (int ni = 0; ni < 8; ni++) mma_bf(oacc[ni], ash[kc], bv[1][ni]);
#pragma unroll
            for (int ni = 0; ni < 8; ni++) mma_bf(oacc[ni], asl[kc], bv[0][ni]);
        }
    }

    __syncthreads();
    {
        const size_t soff = ((size_t)bh * NCHUNK + ci) * HD * HD;
#pragma unroll
        for (int i2 = 0; i2 < 4; i2++) {
            int job = tid + 256 * i2;
            int p = job >> 9;
            int row = (job >> 3) & 63;
            int seg = job & 7;
            const bf16* src = (p ? g_Stl : g_Sth) + soff + row * HD + seg * 8;
            *(uint4*)(sm + RK(p) + (row * RST + seg * 8) * 2) = *(const uint4*)src;
        }
    }
    __syncthreads();

    float cacc[8][4];
#pragma unroll
    for (int ni = 0; ni < 8; ni++)
#pragma unroll
        for (int q = 0; q < 4; q++) cacc[ni][q] = 0.f;
#pragma unroll
    for (int kc = 0; kc < 4; kc++) {
        uint32_t bs[2][8][2];
#pragma unroll
        for (int p = 0; p < 2; p++)
#pragma unroll
            for (int na = 0; na < 4; na++) {
                int row = kc * 16 + ((l >> 3) & 1) * 8 + (l & 7);
                int col = na * 16 + (l >> 4) * 8;
                uint32_t r4[4];
                ldsm4t(r4, sb + RK(p) + (row * RST + col) * 2);
                bs[p][na * 2][0] = r4[0]; bs[p][na * 2][1] = r4[1];
                bs[p][na * 2 + 1][0] = r4[2]; bs[p][na * 2 + 1][1] = r4[3];
            }
#pragma unroll
        for (int ni = 0; ni < 8; ni++) mma_bf(cacc[ni], aq[0][kc], bs[0][ni]);
#pragma unroll
        for (int ni = 0; ni < 8; ni++) mma_bf(cacc[ni], aq[0][kc], bs[1][ni]);
#pragma unroll
        for (int ni = 0; ni < 8; ni++) mma_bf(cacc[ni], aq[1][kc], bs[0][ni]);
    }
    {
        const float w1 = 0.125f * exp2f(lg * (float)(il + 1));
        const float w2 = 0.125f * exp2f(lg * (float)(il + 9));
#pragma unroll
        for (int ni = 0; ni < 8; ni++) {
            oacc[ni][0] += w1 * cacc[ni][0];
            oacc[ni][1] += w1 * cacc[ni][1];
            oacc[ni][2] += w2 * cacc[ni][2];
            oacc[ni][3] += w2 * cacc[ni][3];
        }
    }

#pragma unroll
    for (int ni = 0; ni < 8; ni++) {
        int col = ni * 8 + 2 * tq;
        int r1 = t0 + il, r2 = r1 + 8;
        *(float2*)(g_O + (base + (size_t)r1 * HD + col)) = make_float2(oacc[ni][0], oacc[ni][1]);
        *(float2*)(g_O + (base + (size_t)r2 * HD + col)) = make_float2(oacc[ni][2], oacc[ni][3]);
    }
}

// ---------------------------------------------------------------------------
// GroupNorm over (D,T) per (b,h); writes split bf16 into (B,T,C).
// ---------------------------------------------------------------------------
__global__ __launch_bounds__(256) void groupnorm_kernel(const float* __restrict__ gnw,
                                                        const float* __restrict__ gnb) {
    const int bh = blockIdx.x;
    const int b = bh >> 4, h = bh & 15;
    const float* bsrc = g_O + (size_t)bh * (NT * HD);
    const int tid = threadIdx.x;

    double s1 = 0.0, s2 = 0.0;
    for (int i = tid; i < NT * HD; i += 256) {
        float v = bsrc[i];
        s1 += v;
        s2 += (double)v * v;
    }
    __shared__ double r1[256], r2[256];
    r1[tid] = s1; r2[tid] = s2;
    __syncthreads();
    for (int s = 128; s > 0; s >>= 1) {
        if (tid < s) { r1[tid] += r1[tid + s]; r2[tid] += r2[tid + s]; }
        __syncthreads();
    }
    __shared__ float smu, srs;
    if (tid == 0) {
        double mu  = r1[0] / (double)(NT * HD);
        double var = r2[0] / (double)(NT * HD) - mu * mu;
        smu = (float)mu;
        srs = (float)(1.0 / sqrt(var + 1e-5));
    }
    __syncthreads();
    float mu = smu, rs = srs;
    for (int i = tid; i < NT * HD; i += 256) {
        int t = i >> 6, d = i & 63;
        int c = h * 64 + d;
        float v = (bsrc[i] - mu) * rs * gnw[c] + gnb[c];
        size_t idx = ((size_t)b * NT + t) * NC + c;
        bf16 hv = __float2bfloat16(v);
        g_Ynh[idx] = hv;
        g_Ynl[idx] = __float2bfloat16(v - __bfloat162float(hv));
    }
}

// ---------------------------------------------------------------------------
// Launch. Launch #4 = gemm_mma<0> (the profiled slot, empirically).
// ---------------------------------------------------------------------------
extern "C" void kernel_launch(void* const* d_in, const int* in_sizes, int n_in,
                              void* d_out, int out_size) {
    const float* x   = (const float*)d_in[0];
    const float* Wq  = (const float*)d_in[1];
    const float* Wk  = (const float*)d_in[2];
    const float* Wv  = (const float*)d_in[3];
    const float* Wo  = (const float*)d_in[4];
    const float* gnw = (const float*)d_in[5];
    const float* gnb = (const float*)d_in[6];
    float* out = (float*)d_out;

    cudaFuncSetAttribute(gemm_mma<0>, cudaFuncAttributeMaxDynamicSharedMemorySize, GEMM_SMEM);
    cudaFuncSetAttribute(gemm_mma<1>, cudaFuncAttributeMaxDynamicSharedMemorySize, GEMM_SMEM);
    cudaFuncSetAttribute(chunk_state_kernel, cudaFuncAttributeMaxDynamicSharedMemorySize, CHUNK_SMEM);
    cudaFuncSetAttribute(retention_chunk_kernel, cudaFuncAttributeMaxDynamicSharedMemorySize, RET_SMEM);

    split_x_kernel<<<MTOT * NC / 4 / 256, 256>>>((const float4*)x);            // 1
    split_w2_kernel<<<2 * NC * NC / 4 / 256, 256>>>((const float4*)Wq,
                                                    (const float4*)Wk, 0, 1);  // 2
    split_w2_kernel<<<2 * NC * NC / 4 / 256, 256>>>((const float4*)Wv,
                                                    (const float4*)Wo, 2, 3);  // 3
    gemm_mma<0><<<dim3(MTOT / 128, NC / 128, 3), 256, GEMM_SMEM>>>(nullptr);   // 4 (profiled)
    chunk_state_kernel<<<dim3(NCHUNK, NB * NH), 128, CHUNK_SMEM>>>();          // 5
    state_scan_kernel<<<NB * NH, 256>>>();                                     // 6
    retention_chunk_kernel<<<dim3(NCHUNK, NB * NH), 256, RET_SMEM>>>();        // 7
    groupnorm_kernel<<<NB * NH, 256>>>(gnw, gnb);                              // 8
    gemm_mma<1><<<dim3(MTOT / 128, NC / 128, 1), 256, GEMM_SMEM>>>(out);       // 9
}

// round 7
// speedup vs baseline: 2.6522x; 1.0911x over previous
#include <cuda_runtime.h>
#include <cuda_bf16.h>
#include <math.h>
#include <cstdint>

#define NB 2
#define NT 2048
#define NH 16
#define HD 64
#define NC 1024
#define MTOT (NB*NT)   // 4096
#define NCHUNK 16      // T / 128

typedef __nv_bfloat16  bf16;
typedef __nv_bfloat162 bf162;

// ---------------------------------------------------------------------------
// Scratch (allocation-free rule: __device__ globals)
// ---------------------------------------------------------------------------
__device__ __align__(16) bf16 g_Xh[MTOT*NC],  g_Xl[MTOT*NC];
__device__ __align__(16) bf16 g_Wh[4*NC*NC],  g_Wl[4*NC*NC];
__device__ __align__(16) bf16 g_Qh[NB*NH*NT*HD], g_Ql[NB*NH*NT*HD];
__device__ __align__(16) bf16 g_Kh[NB*NH*NT*HD], g_Kl[NB*NH*NT*HD];
__device__ __align__(16) bf16 g_Vh[NB*NH*NT*HD], g_Vl[NB*NH*NT*HD];
__device__ __align__(16) float g_O[NB*NH*NT*HD];
__device__ __align__(16) bf16 g_Ynh[MTOT*NC], g_Ynl[MTOT*NC];
__device__ __align__(16) float g_U[NB*NH*NCHUNK*HD*HD];
__device__ __align__(16) bf16 g_Sth[NB*NH*NCHUNK*HD*HD];
__device__ __align__(16) bf16 g_Stl[NB*NH*NCHUNK*HD*HD];

// ---------------------------------------------------------------------------
// Helpers
// ---------------------------------------------------------------------------
__device__ __forceinline__ uint32_t smaddr(const void* p) {
    uint32_t a;
    asm("{ .reg .u64 t; cvta.to.shared.u64 t, %1; cvt.u32.u64 %0, t; }"
        : "=r"(a) : "l"(p));
    return a;
}
__device__ __forceinline__ void ldsm4(uint32_t r[4], uint32_t a) {
    asm volatile("ldmatrix.sync.aligned.m8n8.x4.shared.b16 {%0,%1,%2,%3}, [%4];"
        : "=r"(r[0]), "=r"(r[1]), "=r"(r[2]), "=r"(r[3]) : "r"(a));
}
__device__ __forceinline__ void ldsm4t(uint32_t r[4], uint32_t a) {
    asm volatile("ldmatrix.sync.aligned.m8n8.x4.trans.shared.b16 {%0,%1,%2,%3}, [%4];"
        : "=r"(r[0]), "=r"(r[1]), "=r"(r[2]), "=r"(r[3]) : "r"(a));
}
__device__ __forceinline__ void mma_bf(float c[4], const uint32_t a[4], const uint32_t b[2]) {
    asm volatile(
        "mma.sync.aligned.m16n8k16.row.col.f32.bf16.bf16.f32 "
        "{%0,%1,%2,%3}, {%4,%5,%6,%7}, {%8,%9}, {%0,%1,%2,%3};"
        : "+f"(c[0]), "+f"(c[1]), "+f"(c[2]), "+f"(c[3])
        : "r"(a[0]), "r"(a[1]), "r"(a[2]), "r"(a[3]), "r"(b[0]), "r"(b[1]));
}
__device__ __forceinline__ uint32_t pk2(float a, float b) {
    bf162 t = __floats2bfloat162_rn(a, b);
    return *reinterpret_cast<uint32_t*>(&t);
}
__device__ __forceinline__ float lg2gamma(int h) {
    double gamma = 1.0 - exp2(-5.0 - 0.5 * (double)h);
    return (float)log2(gamma);
}
__device__ __forceinline__ void cpa16(uint32_t s, const void* g) {
    asm volatile("cp.async.cg.shared.global [%0], [%1], 16;" :: "r"(s), "l"(g));
}
#define CP_COMMIT() asm volatile("cp.async.commit_group;" ::: "memory")
#define CP_WAIT0()  asm volatile("cp.async.wait_group 0;" ::: "memory")

__device__ __forceinline__ void split4(float4 v, uint2& hi, uint2& lo) {
    bf162 h0 = __floats2bfloat162_rn(v.x, v.y);
    bf162 h1 = __floats2bfloat162_rn(v.z, v.w);
    bf162 l0 = __floats2bfloat162_rn(v.x - __bfloat162float(h0.x),
                                     v.y - __bfloat162float(h0.y));
    bf162 l1 = __floats2bfloat162_rn(v.z - __bfloat162float(h1.x),
                                     v.w - __bfloat162float(h1.y));
    hi.x = *(uint32_t*)&h0; hi.y = *(uint32_t*)&h1;
    lo.x = *(uint32_t*)&l0; lo.y = *(uint32_t*)&l1;
}

// ---------------------------------------------------------------------------
// Splits (vectorized)
// ---------------------------------------------------------------------------
__global__ __launch_bounds__(256) void split_x_kernel(const float4* __restrict__ src) {
    int i = blockIdx.x * blockDim.x + threadIdx.x;
    if (i >= MTOT * NC / 4) return;
    uint2 hi, lo;
    split4(src[i], hi, lo);
    *(uint2*)(g_Xh + 4 * (size_t)i) = hi;
    *(uint2*)(g_Xl + 4 * (size_t)i) = lo;
}
__global__ __launch_bounds__(256) void split_w2_kernel(const float4* __restrict__ a,
                                                       const float4* __restrict__ b,
                                                       int wa, int wb) {
    const int n = NC * NC / 4;
    int i = blockIdx.x * blockDim.x + threadIdx.x;
    if (i >= 2 * n) return;
    const float4* src = (i < n) ? a : b;
    int widx = (i < n) ? wa : wb;
    int j = (i < n) ? i : i - n;
    uint2 hi, lo;
    split4(src[j], hi, lo);
    *(uint2*)(g_Wh + (size_t)widx * NC * NC + 4 * (size_t)j) = hi;
    *(uint2*)(g_Wl + (size_t)widx * NC * NC + 4 * (size_t)j) = lo;
}

// ---------------------------------------------------------------------------
// bf16x3 GEMM with cp.async 2-stage pipeline, 2 CTAs/SM.
// C[r,n] = sum_k A[r,k]*W[n,k]; block 128x128, 8 warps, warp tile 32x64.
// B-part fragments loaded one part at a time to cap register pressure.
// ---------------------------------------------------------------------------
#define AST 40
#define KCH 32
#define SOA(buf,p) ((buf)*20480 + (p)*10240)
#define SOB(buf,p) (40960 + (buf)*20480 + (p)*10240)
#define GEMM_SMEM 81920

template<int MODE>
__global__ __launch_bounds__(256, 2) void gemm_mma(float* __restrict__ Cf) {
    extern __shared__ __align__(16) char sm[];
    const int tid = threadIdx.x, l = tid & 31, wid = tid >> 5;
    const int wm = wid & 3, wn = wid >> 2;
    const int r0 = blockIdx.x * 128, n0 = blockIdx.y * 128;
    const int z = blockIdx.z;
    const int wsel = (MODE == 0) ? z : 3;

    const bf16* Ah = (MODE == 0) ? g_Xh : g_Ynh;
    const bf16* Al = (MODE == 0) ? g_Xl : g_Ynl;
    const bf16* Wh = g_Wh + (size_t)wsel * NC * NC;
    const bf16* Wl = g_Wl + (size_t)wsel * NC * NC;
    const uint32_t sb = smaddr(sm);

    float acc[2][8][4];
#pragma unroll
    for (int mi = 0; mi < 2; mi++)
#pragma unroll
        for (int ni = 0; ni < 8; ni++)
#pragma unroll
            for (int q = 0; q < 4; q++) acc[mi][ni][q] = 0.f;

    auto load_chunk = [&](int kb, int buf) {
#pragma unroll
        for (int i = 0; i < 8; i++) {
            int j = tid + 256 * i;
            int row = (j >> 2) & 127, seg = j & 3, part = (j >> 9) & 1;
            if (j < 1024) {
                const bf16* src = (part ? Al : Ah) + (size_t)(r0 + row) * NC + kb + seg * 8;
                cpa16(sb + SOA(buf, part) + (row * AST + seg * 8) * 2, src);
            } else {
                const bf16* src = (part ? Wl : Wh) + (size_t)(n0 + row) * NC + kb + seg * 8;
                cpa16(sb + SOB(buf, part) + (row * AST + seg * 8) * 2, src);
            }
        }
    };

    load_chunk(0, 0);
    CP_COMMIT();

    for (int c = 0; c < KCH; c++) {
        const int buf = c & 1;
        CP_WAIT0();
        __syncthreads();
        if (c + 1 < KCH) {
            load_chunk((c + 1) * 32, buf ^ 1);
            CP_COMMIT();
        }
#pragma unroll
        for (int ks = 0; ks < 32; ks += 16) {
            uint32_t af[2][2][4];
#pragma unroll
            for (int p = 0; p < 2; p++)
#pragma unroll
                for (int mi = 0; mi < 2; mi++) {
                    int row = wm * 32 + mi * 16 + (l & 7) + ((l >> 3) & 1) * 8;
                    int col = ks + (l >> 4) * 8;
                    ldsm4(af[p][mi], sb + SOA(buf, p) + (row * AST + col) * 2);
                }
            // B part 0 (hi): hi*hi and lo*hi
            {
                uint32_t b0[8][2];
#pragma unroll
                for (int na = 0; na < 4; na++) {
                    int row = wn * 64 + na * 16 + (l >> 4) * 8 + (l & 7);
                    int col = ks + ((l >> 3) & 1) * 8;
                    uint32_t r4[4];
                    ldsm4(r4, sb + SOB(buf, 0) + (row * AST + col) * 2);
                    b0[na * 2][0] = r4[0]; b0[na * 2][1] = r4[1];
                    b0[na * 2 + 1][0] = r4[2]; b0[na * 2 + 1][1] = r4[3];
                }
#pragma unroll
                for (int mi = 0; mi < 2; mi++)
#pragma unroll
                    for (int ni = 0; ni < 8; ni++) mma_bf(acc[mi][ni], af[0][mi], b0[ni]);
#pragma unroll
                for (int mi = 0; mi < 2; mi++)
#pragma unroll
                    for (int ni = 0; ni < 8; ni++) mma_bf(acc[mi][ni], af[1][mi], b0[ni]);
            }
            // B part 1 (lo): hi*lo
            {
                uint32_t b1[8][2];
#pragma unroll
                for (int na = 0; na < 4; na++) {
                    int row = wn * 64 + na * 16 + (l >> 4) * 8 + (l & 7);
                    int col = ks + ((l >> 3) & 1) * 8;
                    uint32_t r4[4];
                    ldsm4(r4, sb + SOB(buf, 1) + (row * AST + col) * 2);
                    b1[na * 2][0] = r4[0]; b1[na * 2][1] = r4[1];
                    b1[na * 2 + 1][0] = r4[2]; b1[na * 2 + 1][1] = r4[3];
                }
#pragma unroll
                for (int mi = 0; mi < 2; mi++)
#pragma unroll
                    for (int ni = 0; ni < 8; ni++) mma_bf(acc[mi][ni], af[0][mi], b1[ni]);
            }
        }
    }

    const int g = l >> 2, tq = l & 3;
    bf16* oh = nullptr; bf16* ol = nullptr;
    if (MODE == 0) {
        oh = (z == 0) ? g_Qh : (z == 1) ? g_Kh : g_Vh;
        ol = (z == 0) ? g_Ql : (z == 1) ? g_Kl : g_Vl;
    }
#pragma unroll
    for (int mi = 0; mi < 2; mi++)
#pragma unroll
        for (int ni = 0; ni < 8; ni++) {
            int rbase = r0 + wm * 32 + mi * 16 + g;
            int n = n0 + wn * 64 + ni * 8 + 2 * tq;
#pragma unroll
            for (int rr = 0; rr < 2; rr++) {
                int row = rbase + rr * 8;
                float v0 = acc[mi][ni][rr * 2 + 0];
                float v1 = acc[mi][ni][rr * 2 + 1];
                if (MODE == 0) {
                    int b = row >> 11, t = row & (NT - 1);
                    int hh = n >> 6, d = n & 63;
                    size_t idx = (((size_t)b * NH + hh) * NT + t) * HD + d;
                    bf16 h0 = __float2bfloat16(v0);
                    bf16 h1 = __float2bfloat16(v1);
                    bf162 hv; hv.x = h0; hv.y = h1;
                    bf162 lv;
                    lv.x = __float2bfloat16(v0 - __bfloat162float(h0));
                    lv.y = __float2bfloat16(v1 - __bfloat162float(h1));
                    *(bf162*)(oh + idx) = hv;
                    *(bf162*)(ol + idx) = lv;
                } else {
                    *(float2*)(Cf + (size_t)row * NC + n) = make_float2(v0, v1);
                }
            }
        }
}

// ---------------------------------------------------------------------------
// Phase A: per-chunk KV summary
// ---------------------------------------------------------------------------
#define CST 72
#define CWK(p) ((p)*18432)
#define CV(p)  (36864 + (p)*18432)
#define CHUNK_SMEM 73728

__global__ __launch_bounds__(128) void chunk_state_kernel() {
    extern __shared__ __align__(16) char sm[];
    const int tid = threadIdx.x, l = tid & 31, wid = tid >> 5;
    const int ci = blockIdx.x, bh = blockIdx.y, h = bh & (NH - 1);
    const float lg = lg2gamma(h);
    const uint32_t sb = smaddr(sm);
    const size_t base = (size_t)bh * NT * HD + (size_t)ci * 128 * HD;

    {
        const int j = tid;
        const float w = exp2f(lg * (float)(127 - j));
        const bf16* Kh = g_Kh + base + (size_t)j * HD;
        const bf16* Kl = g_Kl + base + (size_t)j * HD;
        const bf16* Vh = g_Vh + base + (size_t)j * HD;
        const bf16* Vl = g_Vl + base + (size_t)j * HD;
#pragma unroll
        for (int seg = 0; seg < 8; seg++) {
            uint4 khv = *(const uint4*)(Kh + seg * 8);
            uint4 klv = *(const uint4*)(Kl + seg * 8);
            const bf162* kh2 = (const bf162*)&khv;
            const bf162* kl2 = (const bf162*)&klv;
            uint32_t oh[4], ol[4];
#pragma unroll
            for (int q = 0; q < 4; q++) {
                float f0 = __bfloat162float(kh2[q].x) + __bfloat162float(kl2[q].x);
                float f1 = __bfloat162float(kh2[q].y) + __bfloat162float(kl2[q].y);
                f0 *= w; f1 *= w;
                bf16 h0 = __float2bfloat16(f0), h1 = __float2bfloat16(f1);
                float r0 = f0 - __bfloat162float(h0);
                float r1 = f1 - __bfloat162float(h1);
                ol[q] = pk2(r0, r1);
                bf162 hv; hv.x = h0; hv.y = h1;
                oh[q] = *(uint32_t*)&hv;
            }
            *(uint4*)(sm + CWK(0) + (j * CST + seg * 8) * 2) = *(uint4*)oh;
            *(uint4*)(sm + CWK(1) + (j * CST + seg * 8) * 2) = *(uint4*)ol;
            *(uint4*)(sm + CV(0) + (j * CST + seg * 8) * 2) = *(const uint4*)(Vh + seg * 8);
            *(uint4*)(sm + CV(1) + (j * CST + seg * 8) * 2) = *(const uint4*)(Vl + seg * 8);
        }
    }
    __syncthreads();

    float acc[8][4];
#pragma unroll
    for (int ni = 0; ni < 8; ni++)
#pragma unroll
        for (int q = 0; q < 4; q++) acc[ni][q] = 0.f;

#pragma unroll
    for (int ks = 0; ks < 8; ks++) {
        uint32_t ah[4], al[4];
        {
            int row = ks * 16 + (l & 7) + ((l >> 4) & 1) * 8;
            int col = 16 * wid + ((l >> 3) & 1) * 8;
            ldsm4t(ah, sb + CWK(0) + (row * CST + col) * 2);
            ldsm4t(al, sb + CWK(1) + (row * CST + col) * 2);
        }
        uint32_t bv[2][8][2];
#pragma unroll
        for (int p = 0; p < 2; p++)
#pragma unroll
            for (int na = 0; na < 4; na++) {
                int row = ks * 16 + ((l >> 3) & 1) * 8 + (l & 7);
                int col = na * 16 + (l >> 4) * 8;
                uint32_t r4[4];
                ldsm4t(r4, sb + CV(p) + (row * CST + col) * 2);
                bv[p][na * 2][0] = r4[0]; bv[p][na * 2][1] = r4[1];
                bv[p][na * 2 + 1][0] = r4[2]; bv[p][na * 2 + 1][1] = r4[3];
            }
#pragma unroll
        for (int ni = 0; ni < 8; ni++) mma_bf(acc[ni], ah, bv[0][ni]);
#pragma unroll
        for (int ni = 0; ni < 8; ni++) mma_bf(acc[ni], ah, bv[1][ni]);
#pragma unroll
        for (int ni = 0; ni < 8; ni++) mma_bf(acc[ni], al, bv[0][ni]);
    }

    float* U = g_U + ((size_t)bh * NCHUNK + ci) * HD * HD;
    const int g = l >> 2, tq = l & 3;
#pragma unroll
    for (int ni = 0; ni < 8; ni++) {
        int col = ni * 8 + 2 * tq;
        int row1 = 16 * wid + g, row2 = row1 + 8;
        *(float2*)(U + row1 * HD + col) = make_float2(acc[ni][0], acc[ni][1]);
        *(float2*)(U + row2 * HD + col) = make_float2(acc[ni][2], acc[ni][3]);
    }
}

// ---------------------------------------------------------------------------
// Phase B: prefix scan over chunks.
// ---------------------------------------------------------------------------
__global__ __launch_bounds__(256) void state_scan_kernel() {
    const int bh = blockIdx.x, h = bh & (NH - 1);
    const float lg = lg2gamma(h);
    const float g128 = exp2f(lg * 128.0f);
    const int tid = threadIdx.x;

    float st[16];
#pragma unroll
    for (int k = 0; k < 16; k++) st[k] = 0.f;

    for (int c = 0; c < NCHUNK; c++) {
        const size_t off = ((size_t)bh * NCHUNK + c) * HD * HD;
#pragma unroll
        for (int k = 0; k < 16; k++) {
            int idx = tid + 256 * k;
            bf16 hv = __float2bfloat16(st[k]);
            g_Sth[off + idx] = hv;
            g_Stl[off + idx] = __float2bfloat16(st[k] - __bfloat162float(hv));
            st[k] = g128 * st[k] + g_U[off + idx];
        }
    }
}

// ---------------------------------------------------------------------------
// Phase C: intra-chunk quadratic + cross-chunk state term.
// ---------------------------------------------------------------------------
#define RST 72
#define RQ(p)  ((p)*18432)
#define RK(p)  (36864 + (p)*9216)
#define RV(p)  (55296 + (p)*9216)
#define RDW    73728
#define RET_SMEM 74752

__global__ __launch_bounds__(256) void retention_chunk_kernel() {
    extern __shared__ __align__(16) char sm[];
    float* dw = (float*)(sm + RDW);
    const int tid = threadIdx.x, l = tid & 31, wid = tid >> 5;
    const int bh = blockIdx.y, h = bh & (NH - 1);
    const int ci = blockIdx.x;
    const int t0 = ci * 128;
    const float lg = lg2gamma(h);
    const uint32_t sb = smaddr(sm);
    const size_t base = (size_t)bh * NT * HD;

#pragma unroll
    for (int p = 0; p < 2; p++) {
        const bf16* Qp = (p ? g_Ql : g_Qh) + base + (size_t)t0 * HD;
#pragma unroll
        for (int i = 0; i < 4; i++) {
            int flat = tid + 256 * i;
            int row = flat >> 3, seg = flat & 7;
            uint4 v = *(const uint4*)(Qp + (size_t)row * HD + seg * 8);
            *(uint4*)(sm + RQ(p) + (row * RST + seg * 8) * 2) = v;
        }
    }
    __syncthreads();

    uint32_t aq[2][4][4];
#pragma unroll
    for (int p = 0; p < 2; p++)
#pragma unroll
        for (int kc = 0; kc < 4; kc++) {
            int row = wid * 16 + (l & 7) + ((l >> 3) & 1) * 8;
            int col = kc * 16 + (l >> 4) * 8;
            ldsm4(aq[p][kc], sb + RQ(p) + (row * RST + col) * 2);
        }

    float oacc[8][4];
#pragma unroll
    for (int ni = 0; ni < 8; ni++)
#pragma unroll
        for (int q = 0; q < 4; q++) oacc[ni][q] = 0.f;

    const int g = l >> 2, tq = l & 3;
    const int il = 16 * wid + g;

    for (int s0 = t0; s0 <= t0 + 64; s0 += 64) {
        __syncthreads();
#pragma unroll
        for (int p = 0; p < 2; p++) {
            const bf16* Kp = (p ? g_Kl : g_Kh) + base + (size_t)s0 * HD;
            const bf16* Vp = (p ? g_Vl : g_Vh) + base + (size_t)s0 * HD;
#pragma unroll
            for (int i = 0; i < 2; i++) {
                int flat = tid + 256 * i;
                int row = flat >> 3, seg = flat & 7;
                uint4 kv = *(const uint4*)(Kp + (size_t)row * HD + seg * 8);
                *(uint4*)(sm + RK(p) + (row * RST + seg * 8) * 2) = kv;
                uint4 vv = *(const uint4*)(Vp + (size_t)row * HD + seg * 8);
                *(uint4*)(sm + RV(p) + (row * RST + seg * 8) * 2) = vv;
            }
        }
        if (tid < 192) {
            int diff = t0 - s0 - 63 + tid;
            dw[tid] = (diff >= 0) ? 0.125f * exp2f(lg * (float)diff) : 0.f;
        }
        __syncthreads();

        float sacc[8][4];
#pragma unroll
        for (int ni = 0; ni < 8; ni++)
#pragma unroll
            for (int q = 0; q < 4; q++) sacc[ni][q] = 0.f;
#pragma unroll
        for (int kc = 0; kc < 4; kc++) {
            uint32_t bk[2][8][2];
#pragma unroll
            for (int p = 0; p < 2; p++)
#pragma unroll
                for (int na = 0; na < 4; na++) {
                    int row = na * 16 + (l >> 4) * 8 + (l & 7);
                    int col = kc * 16 + ((l >> 3) & 1) * 8;
                    uint32_t r4[4];
                    ldsm4(r4, sb + RK(p) + (row * RST + col) * 2);
                    bk[p][na * 2][0] = r4[0]; bk[p][na * 2][1] = r4[1];
                    bk[p][na * 2 + 1][0] = r4[2]; bk[p][na * 2 + 1][1] = r4[3];
                }
#pragma unroll
            for (int ni = 0; ni < 8; ni++) mma_bf(sacc[ni], aq[0][kc], bk[0][ni]);
#pragma unroll
            for (int ni = 0; ni < 8; ni++) mma_bf(sacc[ni], aq[0][kc], bk[1][ni]);
#pragma unroll
            for (int ni = 0; ni < 8; ni++) mma_bf(sacc[ni], aq[1][kc], bk[0][ni]);
        }

#pragma unroll
        for (int ni = 0; ni < 8; ni++) {
            int jb = ni * 8 + 2 * tq;
            sacc[ni][0] *= dw[63 + il - jb];
            sacc[ni][1] *= dw[63 + il - (jb + 1)];
            sacc[ni][2] *= dw[63 + il + 8 - jb];
            sacc[ni][3] *= dw[63 + il + 8 - (jb + 1)];
        }

        uint32_t ash[4][4], asl[4][4];
#pragma unroll
        for (int kc = 0; kc < 4; kc++) {
            const float* e0 = sacc[2 * kc];
            const float* e1 = sacc[2 * kc + 1];
            float src[8] = {e0[0], e0[1], e0[2], e0[3], e1[0], e1[1], e1[2], e1[3]};
            float hv[8], lv[8];
#pragma unroll
            for (int q = 0; q < 8; q++) {
                bf16 hb = __float2bfloat16(src[q]);
                hv[q] = __bfloat162float(hb);
                lv[q] = src[q] - hv[q];
            }
            ash[kc][0] = pk2(hv[0], hv[1]); ash[kc][1] = pk2(hv[2], hv[3]);
            ash[kc][2] = pk2(hv[4], hv[5]); ash[kc][3] = pk2(hv[6], hv[7]);
            asl[kc][0] = pk2(lv[0], lv[1]); asl[kc][1] = pk2(lv[2], lv[3]);
            asl[kc][2] = pk2(lv[4], lv[5]); asl[kc][3] = pk2(lv[6], lv[7]);
        }

#pragma unroll
        for (int kc = 0; kc < 4; kc++) {
            uint32_t bv[2][8][2];
#pragma unroll
            for (int p = 0; p < 2; p++)
#pragma unroll
                for (int na = 0; na < 4; na++) {
                    int row = kc * 16 + ((l >> 3) & 1) * 8 + (l & 7);
                    int col = na * 16 + (l >> 4) * 8;
                    uint32_t r4[4];
                    ldsm4t(r4, sb + RV(p) + (row * RST + col) * 2);
                    bv[p][na * 2][0] = r4[0]; bv[p][na * 2][1] = r4[1];
                    bv[p][na * 2 + 1][0] = r4[2]; bv[p][na * 2 + 1][1] = r4[3];
                }
#pragma unroll
            for (int ni = 0; ni < 8; ni++) mma_bf(oacc[ni], ash[kc], bv[0][ni]);
#pragma unroll
            for (int ni = 0; ni < 8; ni++) mma_bf(oacc[ni], ash[kc], bv[1][ni]);
#pragma unroll
            for (int ni = 0; ni < 8; ni++) mma_bf(oacc[ni], asl[kc], bv[0][ni]);
        }
    }

    __syncthreads();
    {
        const size_t soff = ((size_t)bh * NCHUNK + ci) * HD * HD;
#pragma unroll
        for (int i2 = 0; i2 < 4; i2++) {
            int job = tid + 256 * i2;
            int p = job >> 9;
            int row = (job >> 3) & 63;
            int seg = job & 7;
            const bf16* src = (p ? g_Stl : g_Sth) + soff + row * HD + seg * 8;
            *(uint4*)(sm + RK(p) + (row * RST + seg * 8) * 2) = *(const uint4*)src;
        }
    }
    __syncthreads();

    float cacc[8][4];
#pragma unroll
    for (int ni = 0; ni < 8; ni++)
#pragma unroll
        for (int q = 0; q < 4; q++) cacc[ni][q] = 0.f;
#pragma unroll
    for (int kc = 0; kc < 4; kc++) {
        uint32_t bs[2][8][2];
#pragma unroll
        for (int p = 0; p < 2; p++)
#pragma unroll
            for (int na = 0; na < 4; na++) {
                int row = kc * 16 + ((l >> 3) & 1) * 8 + (l & 7);
                int col = na * 16 + (l >> 4) * 8;
                uint32_t r4[4];
                ldsm4t(r4, sb + RK(p) + (row * RST + col) * 2);
                bs[p][na * 2][0] = r4[0]; bs[p][na * 2][1] = r4[1];
                bs[p][na * 2 + 1][0] = r4[2]; bs[p][na * 2 + 1][1] = r4[3];
            }
#pragma unroll
        for (int ni = 0; ni < 8; ni++) mma_bf(cacc[ni], aq[0][kc], bs[0][ni]);
#pragma unroll
        for (int ni = 0; ni < 8; ni++) mma_bf(cacc[ni], aq[0][kc], bs[1][ni]);
#pragma unroll
        for (int ni = 0; ni < 8; ni++) mma_bf(cacc[ni], aq[1][kc], bs[0][ni]);
    }
    {
        const float w1 = 0.125f * exp2f(lg * (float)(il + 1));
        const float w2 = 0.125f * exp2f(lg * (float)(il + 9));
#pragma unroll
        for (int ni = 0; ni < 8; ni++) {
            oacc[ni][0] += w1 * cacc[ni][0];
            oacc[ni][1] += w1 * cacc[ni][1];
            oacc[ni][2] += w2 * cacc[ni][2];
            oacc[ni][3] += w2 * cacc[ni][3];
        }
    }

#pragma unroll
    for (int ni = 0; ni < 8; ni++) {
        int col = ni * 8 + 2 * tq;
        int r1 = t0 + il, r2 = r1 + 8;
        *(float2*)(g_O + (base + (size_t)r1 * HD + col)) = make_float2(oacc[ni][0], oacc[ni][1]);
        *(float2*)(g_O + (base + (size_t)r2 * HD + col)) = make_float2(oacc[ni][2], oacc[ni][3]);
    }
}

// ---------------------------------------------------------------------------
// GroupNorm over (D,T) per (b,h); writes split bf16 into (B,T,C).
// ---------------------------------------------------------------------------
__global__ __launch_bounds__(256) void groupnorm_kernel(const float* __restrict__ gnw,
                                                        const float* __restrict__ gnb) {
    const int bh = blockIdx.x;
    const int b = bh >> 4, h = bh & 15;
    const float* bsrc = g_O + (size_t)bh * (NT * HD);
    const int tid = threadIdx.x;

    double s1 = 0.0, s2 = 0.0;
    for (int i = tid; i < NT * HD; i += 256) {
        float v = bsrc[i];
        s1 += v;
        s2 += (double)v * v;
    }
    __shared__ double r1[256], r2[256];
    r1[tid] = s1; r2[tid] = s2;
    __syncthreads();
    for (int s = 128; s > 0; s >>= 1) {
        if (tid < s) { r1[tid] += r1[tid + s]; r2[tid] += r2[tid + s]; }
        __syncthreads();
    }
    __shared__ float smu, srs;
    if (tid == 0) {
        double mu  = r1[0] / (double)(NT * HD);
        double var = r2[0] / (double)(NT * HD) - mu * mu;
        smu = (float)mu;
        srs = (float)(1.0 / sqrt(var + 1e-5));
    }
    __syncthreads();
    float mu = smu, rs = srs;
    for (int i = tid; i < NT * HD; i += 256) {
        int t = i >> 6, d = i & 63;
        int c = h * 64 + d;
        float v = (bsrc[i] - mu) * rs * gnw[c] + gnb[c];
        size_t idx = ((size_t)b * NT + t) * NC + c;
        bf16 hv = __float2bfloat16(v);
        g_Ynh[idx] = hv;
        g_Ynl[idx] = __float2bfloat16(v - __bfloat162float(hv));
    }
}

// ---------------------------------------------------------------------------
// Launch. Launch #4 = gemm_mma<0> (profiled slot).
// ---------------------------------------------------------------------------
extern "C" void kernel_launch(void* const* d_in, const int* in_sizes, int n_in,
                              void* d_out, int out_size) {
    const float* x   = (const float*)d_in[0];
    const float* Wq  = (const float*)d_in[1];
    const float* Wk  = (const float*)d_in[2];
    const float* Wv  = (const float*)d_in[3];
    const float* Wo  = (const float*)d_in[4];
    const float* gnw = (const float*)d_in[5];
    const float* gnb = (const float*)d_in[6];
    float* out = (float*)d_out;

    cudaFuncSetAttribute(gemm_mma<0>, cudaFuncAttributeMaxDynamicSharedMemorySize, GEMM_SMEM);
    cudaFuncSetAttribute(gemm_mma<1>, cudaFuncAttributeMaxDynamicSharedMemorySize, GEMM_SMEM);
    cudaFuncSetAttribute(chunk_state_kernel, cudaFuncAttributeMaxDynamicSharedMemorySize, CHUNK_SMEM);
    cudaFuncSetAttribute(retention_chunk_kernel, cudaFuncAttributeMaxDynamicSharedMemorySize, RET_SMEM);

    split_x_kernel<<<MTOT * NC / 4 / 256, 256>>>((const float4*)x);            // 1
    split_w2_kernel<<<2 * NC * NC / 4 / 256, 256>>>((const float4*)Wq,
                                                    (const float4*)Wk, 0, 1);  // 2
    split_w2_kernel<<<2 * NC * NC / 4 / 256, 256>>>((const float4*)Wv,
                                                    (const float4*)Wo, 2, 3);  // 3
    gemm_mma<0><<<dim3(MTOT / 128, NC / 128, 3), 256, GEMM_SMEM>>>(nullptr);   // 4 (profiled)
    chunk_state_kernel<<<dim3(NCHUNK, NB * NH), 128, CHUNK_SMEM>>>();          // 5
    state_scan_kernel<<<NB * NH, 256>>>();                                     // 6
    retention_chunk_kernel<<<dim3(NCHUNK, NB * NH), 256, RET_SMEM>>>();        // 7
    groupnorm_kernel<<<NB * NH, 256>>>(gnw, gnb);                              // 8
    gemm_mma<1><<<dim3(MTOT / 128, NC / 128, 1), 256, GEMM_SMEM>>>(out);       // 9
}

// round 8
// speedup vs baseline: 3.7340x; 1.4079x over previous
#include <cuda_runtime.h>
#include <cuda_bf16.h>
#include <math.h>
#include <cstdint>

#define NB 2
#define NT 2048
#define NH 16
#define HD 64
#define NC 1024
#define MTOT (NB*NT)   // 4096
#define NCHUNK 16      // T / 128

typedef __nv_bfloat16  bf16;
typedef __nv_bfloat162 bf162;

// ---------------------------------------------------------------------------
// Scratch (allocation-free rule: __device__ globals)
// ---------------------------------------------------------------------------
__device__ __align__(16) bf16 g_Xh[MTOT*NC],  g_Xl[MTOT*NC];
__device__ __align__(16) bf16 g_Wh[4*NC*NC],  g_Wl[4*NC*NC];
__device__ __align__(16) bf16 g_Qh[NB*NH*NT*HD], g_Ql[NB*NH*NT*HD];
__device__ __align__(16) bf16 g_Kh[NB*NH*NT*HD], g_Kl[NB*NH*NT*HD];
__device__ __align__(16) bf16 g_Vh[NB*NH*NT*HD], g_Vl[NB*NH*NT*HD];
__device__ __align__(16) float g_O[NB*NH*NT*HD];
__device__ __align__(16) bf16 g_Ynh[MTOT*NC], g_Ynl[MTOT*NC];
__device__ __align__(16) float g_U[NB*NH*NCHUNK*HD*HD];
__device__ double2 g_gnp[NB*NH*8];     // groupnorm partial sums

// ---------------------------------------------------------------------------
// Helpers
// ---------------------------------------------------------------------------
__device__ __forceinline__ uint32_t smaddr(const void* p) {
    uint32_t a;
    asm("{ .reg .u64 t; cvta.to.shared.u64 t, %1; cvt.u32.u64 %0, t; }"
        : "=r"(a) : "l"(p));
    return a;
}
__device__ __forceinline__ void ldsm4(uint32_t r[4], uint32_t a) {
    asm volatile("ldmatrix.sync.aligned.m8n8.x4.shared.b16 {%0,%1,%2,%3}, [%4];"
        : "=r"(r[0]), "=r"(r[1]), "=r"(r[2]), "=r"(r[3]) : "r"(a));
}
__device__ __forceinline__ void ldsm4t(uint32_t r[4], uint32_t a) {
    asm volatile("ldmatrix.sync.aligned.m8n8.x4.trans.shared.b16 {%0,%1,%2,%3}, [%4];"
        : "=r"(r[0]), "=r"(r[1]), "=r"(r[2]), "=r"(r[3]) : "r"(a));
}
__device__ __forceinline__ void mma_bf(float c[4], const uint32_t a[4], const uint32_t b[2]) {
    asm volatile(
        "mma.sync.aligned.m16n8k16.row.col.f32.bf16.bf16.f32 "
        "{%0,%1,%2,%3}, {%4,%5,%6,%7}, {%8,%9}, {%0,%1,%2,%3};"
        : "+f"(c[0]), "+f"(c[1]), "+f"(c[2]), "+f"(c[3])
        : "r"(a[0]), "r"(a[1]), "r"(a[2]), "r"(a[3]), "r"(b[0]), "r"(b[1]));
}
__device__ __forceinline__ uint32_t pk2(float a, float b) {
    bf162 t = __floats2bfloat162_rn(a, b);
    return *reinterpret_cast<uint32_t*>(&t);
}
__device__ __forceinline__ float lg2gamma(int h) {
    double gamma = 1.0 - exp2(-5.0 - 0.5 * (double)h);
    return (float)log2(gamma);
}
__device__ __forceinline__ void cpa16(uint32_t s, const void* g) {
    asm volatile("cp.async.cg.shared.global [%0], [%1], 16;" :: "r"(s), "l"(g));
}
#define CP_COMMIT() asm volatile("cp.async.commit_group;" ::: "memory")
#define CP_WAIT0()  asm volatile("cp.async.wait_group 0;" ::: "memory")

__device__ __forceinline__ void split4(float4 v, uint2& hi, uint2& lo) {
    bf162 h0 = __floats2bfloat162_rn(v.x, v.y);
    bf162 h1 = __floats2bfloat162_rn(v.z, v.w);
    bf162 l0 = __floats2bfloat162_rn(v.x - __bfloat162float(h0.x),
                                     v.y - __bfloat162float(h0.y));
    bf162 l1 = __floats2bfloat162_rn(v.z - __bfloat162float(h1.x),
                                     v.w - __bfloat162float(h1.y));
    hi.x = *(uint32_t*)&h0; hi.y = *(uint32_t*)&h1;
    lo.x = *(uint32_t*)&l0; lo.y = *(uint32_t*)&l1;
}

// ---------------------------------------------------------------------------
// Fused split: x and all 4 weights in one launch.
// ---------------------------------------------------------------------------
#define NX4 (MTOT*NC/4)       // 1048576
#define NW4 (NC*NC/4)         // 262144

__global__ __launch_bounds__(256) void split_all_kernel(
    const float4* __restrict__ x,  const float4* __restrict__ wq,
    const float4* __restrict__ wk, const float4* __restrict__ wv,
    const float4* __restrict__ wo)
{
    int i = blockIdx.x * 256 + threadIdx.x;
    uint2 hi, lo;
    if (i < NX4) {
        split4(x[i], hi, lo);
        *(uint2*)(g_Xh + 4 * (size_t)i) = hi;
        *(uint2*)(g_Xl + 4 * (size_t)i) = lo;
    } else {
        int j = i - NX4;
        int widx = j >> 18;
        int e = j & (NW4 - 1);
        const float4* w = (widx == 0) ? wq : (widx == 1) ? wk : (widx == 2) ? wv : wo;
        split4(w[e], hi, lo);
        *(uint2*)(g_Wh + (size_t)widx * NC * NC + 4 * (size_t)e) = hi;
        *(uint2*)(g_Wl + (size_t)widx * NC * NC + 4 * (size_t)e) = lo;
    }
}

// ---------------------------------------------------------------------------
// bf16x3 GEMM with cp.async 2-stage pipeline, 2 CTAs/SM (unchanged from R7).
// ---------------------------------------------------------------------------
#define AST 40
#define KCH 32
#define SOA(buf,p) ((buf)*20480 + (p)*10240)
#define SOB(buf,p) (40960 + (buf)*20480 + (p)*10240)
#define GEMM_SMEM 81920

template<int MODE>
__global__ __launch_bounds__(256, 2) void gemm_mma(float* __restrict__ Cf) {
    extern __shared__ __align__(16) char sm[];
    const int tid = threadIdx.x, l = tid & 31, wid = tid >> 5;
    const int wm = wid & 3, wn = wid >> 2;
    const int r0 = blockIdx.x * 128, n0 = blockIdx.y * 128;
    const int z = blockIdx.z;
    const int wsel = (MODE == 0) ? z : 3;

    const bf16* Ah = (MODE == 0) ? g_Xh : g_Ynh;
    const bf16* Al = (MODE == 0) ? g_Xl : g_Ynl;
    const bf16* Wh = g_Wh + (size_t)wsel * NC * NC;
    const bf16* Wl = g_Wl + (size_t)wsel * NC * NC;
    const uint32_t sb = smaddr(sm);

    float acc[2][8][4];
#pragma unroll
    for (int mi = 0; mi < 2; mi++)
#pragma unroll
        for (int ni = 0; ni < 8; ni++)
#pragma unroll
            for (int q = 0; q < 4; q++) acc[mi][ni][q] = 0.f;

    auto load_chunk = [&](int kb, int buf) {
#pragma unroll
        for (int i = 0; i < 8; i++) {
            int j = tid + 256 * i;
            int row = (j >> 2) & 127, seg = j & 3, part = (j >> 9) & 1;
            if (j < 1024) {
                const bf16* src = (part ? Al : Ah) + (size_t)(r0 + row) * NC + kb + seg * 8;
                cpa16(sb + SOA(buf, part) + (row * AST + seg * 8) * 2, src);
            } else {
                const bf16* src = (part ? Wl : Wh) + (size_t)(n0 + row) * NC + kb + seg * 8;
                cpa16(sb + SOB(buf, part) + (row * AST + seg * 8) * 2, src);
            }
        }
    };

    load_chunk(0, 0);
    CP_COMMIT();

    for (int c = 0; c < KCH; c++) {
        const int buf = c & 1;
        CP_WAIT0();
        __syncthreads();
        if (c + 1 < KCH) {
            load_chunk((c + 1) * 32, buf ^ 1);
            CP_COMMIT();
        }
#pragma unroll
        for (int ks = 0; ks < 32; ks += 16) {
            uint32_t af[2][2][4];
#pragma unroll
            for (int p = 0; p < 2; p++)
#pragma unroll
                for (int mi = 0; mi < 2; mi++) {
                    int row = wm * 32 + mi * 16 + (l & 7) + ((l >> 3) & 1) * 8;
                    int col = ks + (l >> 4) * 8;
                    ldsm4(af[p][mi], sb + SOA(buf, p) + (row * AST + col) * 2);
                }
            {
                uint32_t b0[8][2];
#pragma unroll
                for (int na = 0; na < 4; na++) {
                    int row = wn * 64 + na * 16 + (l >> 4) * 8 + (l & 7);
                    int col = ks + ((l >> 3) & 1) * 8;
                    uint32_t r4[4];
                    ldsm4(r4, sb + SOB(buf, 0) + (row * AST + col) * 2);
                    b0[na * 2][0] = r4[0]; b0[na * 2][1] = r4[1];
                    b0[na * 2 + 1][0] = r4[2]; b0[na * 2 + 1][1] = r4[3];
                }
#pragma unroll
                for (int mi = 0; mi < 2; mi++)
#pragma unroll
                    for (int ni = 0; ni < 8; ni++) mma_bf(acc[mi][ni], af[0][mi], b0[ni]);
#pragma unroll
                for (int mi = 0; mi < 2; mi++)
#pragma unroll
                    for (int ni = 0; ni < 8; ni++) mma_bf(acc[mi][ni], af[1][mi], b0[ni]);
            }
            {
                uint32_t b1[8][2];
#pragma unroll
                for (int na = 0; na < 4; na++) {
                    int row = wn * 64 + na * 16 + (l >> 4) * 8 + (l & 7);
                    int col = ks + ((l >> 3) & 1) * 8;
                    uint32_t r4[4];
                    ldsm4(r4, sb + SOB(buf, 1) + (row * AST + col) * 2);
                    b1[na * 2][0] = r4[0]; b1[na * 2][1] = r4[1];
                    b1[na * 2 + 1][0] = r4[2]; b1[na * 2 + 1][1] = r4[3];
                }
#pragma unroll
                for (int mi = 0; mi < 2; mi++)
#pragma unroll
                    for (int ni = 0; ni < 8; ni++) mma_bf(acc[mi][ni], af[0][mi], b1[ni]);
            }
        }
    }

    const int g = l >> 2, tq = l & 3;
    bf16* oh = nullptr; bf16* ol = nullptr;
    if (MODE == 0) {
        oh = (z == 0) ? g_Qh : (z == 1) ? g_Kh : g_Vh;
        ol = (z == 0) ? g_Ql : (z == 1) ? g_Kl : g_Vl;
    }
#pragma unroll
    for (int mi = 0; mi < 2; mi++)
#pragma unroll
        for (int ni = 0; ni < 8; ni++) {
            int rbase = r0 + wm * 32 + mi * 16 + g;
            int n = n0 + wn * 64 + ni * 8 + 2 * tq;
#pragma unroll
            for (int rr = 0; rr < 2; rr++) {
                int row = rbase + rr * 8;
                float v0 = acc[mi][ni][rr * 2 + 0];
                float v1 = acc[mi][ni][rr * 2 + 1];
                if (MODE == 0) {
                    int b = row >> 11, t = row & (NT - 1);
                    int hh = n >> 6, d = n & 63;
                    size_t idx = (((size_t)b * NH + hh) * NT + t) * HD + d;
                    bf16 h0 = __float2bfloat16(v0);
                    bf16 h1 = __float2bfloat16(v1);
                    bf162 hv; hv.x = h0; hv.y = h1;
                    bf162 lv;
                    lv.x = __float2bfloat16(v0 - __bfloat162float(h0));
                    lv.y = __float2bfloat16(v1 - __bfloat162float(h1));
                    *(bf162*)(oh + idx) = hv;
                    *(bf162*)(ol + idx) = lv;
                } else {
                    *(float2*)(Cf + (size_t)row * NC + n) = make_float2(v0, v1);
                }
            }
        }
}

// ---------------------------------------------------------------------------
// Phase A: per-chunk KV summary (unchanged)
// ---------------------------------------------------------------------------
#define CST 72
#define CWK(p) ((p)*18432)
#define CV(p)  (36864 + (p)*18432)
#define CHUNK_SMEM 73728

__global__ __launch_bounds__(128) void chunk_state_kernel() {
    extern __shared__ __align__(16) char sm[];
    const int tid = threadIdx.x, l = tid & 31, wid = tid >> 5;
    const int ci = blockIdx.x, bh = blockIdx.y, h = bh & (NH - 1);
    const float lg = lg2gamma(h);
    const uint32_t sb = smaddr(sm);
    const size_t base = (size_t)bh * NT * HD + (size_t)ci * 128 * HD;

    {
        const int j = tid;
        const float w = exp2f(lg * (float)(127 - j));
        const bf16* Kh = g_Kh + base + (size_t)j * HD;
        const bf16* Kl = g_Kl + base + (size_t)j * HD;
        const bf16* Vh = g_Vh + base + (size_t)j * HD;
        const bf16* Vl = g_Vl + base + (size_t)j * HD;
#pragma unroll
        for (int seg = 0; seg < 8; seg++) {
            uint4 khv = *(const uint4*)(Kh + seg * 8);
            uint4 klv = *(const uint4*)(Kl + seg * 8);
            const bf162* kh2 = (const bf162*)&khv;
            const bf162* kl2 = (const bf162*)&klv;
            uint32_t oh[4], ol[4];
#pragma unroll
            for (int q = 0; q < 4; q++) {
                float f0 = __bfloat162float(kh2[q].x) + __bfloat162float(kl2[q].x);
                float f1 = __bfloat162float(kh2[q].y) + __bfloat162float(kl2[q].y);
                f0 *= w; f1 *= w;
                bf16 h0 = __float2bfloat16(f0), h1 = __float2bfloat16(f1);
                float r0 = f0 - __bfloat162float(h0);
                float r1 = f1 - __bfloat162float(h1);
                ol[q] = pk2(r0, r1);
                bf162 hv; hv.x = h0; hv.y = h1;
                oh[q] = *(uint32_t*)&hv;
            }
            *(uint4*)(sm + CWK(0) + (j * CST + seg * 8) * 2) = *(uint4*)oh;
            *(uint4*)(sm + CWK(1) + (j * CST + seg * 8) * 2) = *(uint4*)ol;
            *(uint4*)(sm + CV(0) + (j * CST + seg * 8) * 2) = *(const uint4*)(Vh + seg * 8);
            *(uint4*)(sm + CV(1) + (j * CST + seg * 8) * 2) = *(const uint4*)(Vl + seg * 8);
        }
    }
    __syncthreads();

    float acc[8][4];
#pragma unroll
    for (int ni = 0; ni < 8; ni++)
#pragma unroll
        for (int q = 0; q < 4; q++) acc[ni][q] = 0.f;

#pragma unroll
    for (int ks = 0; ks < 8; ks++) {
        uint32_t ah[4], al[4];
        {
            int row = ks * 16 + (l & 7) + ((l >> 4) & 1) * 8;
            int col = 16 * wid + ((l >> 3) & 1) * 8;
            ldsm4t(ah, sb + CWK(0) + (row * CST + col) * 2);
            ldsm4t(al, sb + CWK(1) + (row * CST + col) * 2);
        }
        uint32_t bv[2][8][2];
#pragma unroll
        for (int p = 0; p < 2; p++)
#pragma unroll
            for (int na = 0; na < 4; na++) {
                int row = ks * 16 + ((l >> 3) & 1) * 8 + (l & 7);
                int col = na * 16 + (l >> 4) * 8;
                uint32_t r4[4];
                ldsm4t(r4, sb + CV(p) + (row * CST + col) * 2);
                bv[p][na * 2][0] = r4[0]; bv[p][na * 2][1] = r4[1];
                bv[p][na * 2 + 1][0] = r4[2]; bv[p][na * 2 + 1][1] = r4[3];
            }
#pragma unroll
        for (int ni = 0; ni < 8; ni++) mma_bf(acc[ni], ah, bv[0][ni]);
#pragma unroll
        for (int ni = 0; ni < 8; ni++) mma_bf(acc[ni], ah, bv[1][ni]);
#pragma unroll
        for (int ni = 0; ni < 8; ni++) mma_bf(acc[ni], al, bv[0][ni]);
    }

    float* U = g_U + ((size_t)bh * NCHUNK + ci) * HD * HD;
    const int g = l >> 2, tq = l & 3;
#pragma unroll
    for (int ni = 0; ni < 8; ni++) {
        int col = ni * 8 + 2 * tq;
        int row1 = 16 * wid + g, row2 = row1 + 8;
        *(float2*)(U + row1 * HD + col) = make_float2(acc[ni][0], acc[ni][1]);
        *(float2*)(U + row2 * HD + col) = make_float2(acc[ni][2], acc[ni][3]);
    }
}

// ---------------------------------------------------------------------------
// Phase C: intra-chunk quadratic + cross-chunk state (scan fused in:
// each block accumulates its own state from g_U in fp32).
// ---------------------------------------------------------------------------
#define RST 72
#define RQ(p)  ((p)*18432)
#define RK(p)  (36864 + (p)*9216)
#define RV(p)  (55296 + (p)*9216)
#define RDW    73728
#define RET_SMEM 74752

__global__ __launch_bounds__(256) void retention_chunk_kernel() {
    extern __shared__ __align__(16) char sm[];
    float* dw = (float*)(sm + RDW);
    const int tid = threadIdx.x, l = tid & 31, wid = tid >> 5;
    const int bh = blockIdx.y, h = bh & (NH - 1);
    const int ci = blockIdx.x;
    const int t0 = ci * 128;
    const float lg = lg2gamma(h);
    const uint32_t sb = smaddr(sm);
    const size_t base = (size_t)bh * NT * HD;

#pragma unroll
    for (int p = 0; p < 2; p++) {
        const bf16* Qp = (p ? g_Ql : g_Qh) + base + (size_t)t0 * HD;
#pragma unroll
        for (int i = 0; i < 4; i++) {
            int flat = tid + 256 * i;
            int row = flat >> 3, seg = flat & 7;
            uint4 v = *(const uint4*)(Qp + (size_t)row * HD + seg * 8);
            *(uint4*)(sm + RQ(p) + (row * RST + seg * 8) * 2) = v;
        }
    }
    __syncthreads();

    uint32_t aq[2][4][4];
#pragma unroll
    for (int p = 0; p < 2; p++)
#pragma unroll
        for (int kc = 0; kc < 4; kc++) {
            int row = wid * 16 + (l & 7) + ((l >> 3) & 1) * 8;
            int col = kc * 16 + (l >> 4) * 8;
            ldsm4(aq[p][kc], sb + RQ(p) + (row * RST + col) * 2);
        }

    float oacc[8][4];
#pragma unroll
    for (int ni = 0; ni < 8; ni++)
#pragma unroll
        for (int q = 0; q < 4; q++) oacc[ni][q] = 0.f;

    const int g = l >> 2, tq = l & 3;
    const int il = 16 * wid + g;

    for (int s0 = t0; s0 <= t0 + 64; s0 += 64) {
        __syncthreads();
#pragma unroll
        for (int p = 0; p < 2; p++) {
            const bf16* Kp = (p ? g_Kl : g_Kh) + base + (size_t)s0 * HD;
            const bf16* Vp = (p ? g_Vl : g_Vh) + base + (size_t)s0 * HD;
#pragma unroll
            for (int i = 0; i < 2; i++) {
                int flat = tid + 256 * i;
                int row = flat >> 3, seg = flat & 7;
                uint4 kv = *(const uint4*)(Kp + (size_t)row * HD + seg * 8);
                *(uint4*)(sm + RK(p) + (row * RST + seg * 8) * 2) = kv;
                uint4 vv = *(const uint4*)(Vp + (size_t)row * HD + seg * 8);
                *(uint4*)(sm + RV(p) + (row * RST + seg * 8) * 2) = vv;
            }
        }
        if (tid < 192) {
            int diff = t0 - s0 - 63 + tid;
            dw[tid] = (diff >= 0) ? 0.125f * exp2f(lg * (float)diff) : 0.f;
        }
        __syncthreads();

        float sacc[8][4];
#pragma unroll
        for (int ni = 0; ni < 8; ni++)
#pragma unroll
            for (int q = 0; q < 4; q++) sacc[ni][q] = 0.f;
#pragma unroll
        for (int kc = 0; kc < 4; kc++) {
            uint32_t bk[2][8][2];
#pragma unroll
            for (int p = 0; p < 2; p++)
#pragma unroll
                for (int na = 0; na < 4; na++) {
                    int row = na * 16 + (l >> 4) * 8 + (l & 7);
                    int col = kc * 16 + ((l >> 3) & 1) * 8;
                    uint32_t r4[4];
                    ldsm4(r4, sb + RK(p) + (row * RST + col) * 2);
                    bk[p][na * 2][0] = r4[0]; bk[p][na * 2][1] = r4[1];
                    bk[p][na * 2 + 1][0] = r4[2]; bk[p][na * 2 + 1][1] = r4[3];
                }
#pragma unroll
            for (int ni = 0; ni < 8; ni++) mma_bf(sacc[ni], aq[0][kc], bk[0][ni]);
#pragma unroll
            for (int ni = 0; ni < 8; ni++) mma_bf(sacc[ni], aq[0][kc], bk[1][ni]);
#pragma unroll
            for (int ni = 0; ni < 8; ni++) mma_bf(sacc[ni], aq[1][kc], bk[0][ni]);
        }

#pragma unroll
        for (int ni = 0; ni < 8; ni++) {
            int jb = ni * 8 + 2 * tq;
            sacc[ni][0] *= dw[63 + il - jb];
            sacc[ni][1] *= dw[63 + il - (jb + 1)];
            sacc[ni][2] *= dw[63 + il + 8 - jb];
            sacc[ni][3] *= dw[63 + il + 8 - (jb + 1)];
        }

        uint32_t ash[4][4], asl[4][4];
#pragma unroll
        for (int kc = 0; kc < 4; kc++) {
            const float* e0 = sacc[2 * kc];
            const float* e1 = sacc[2 * kc + 1];
            float src[8] = {e0[0], e0[1], e0[2], e0[3], e1[0], e1[1], e1[2], e1[3]};
            float hv[8], lv[8];
#pragma unroll
            for (int q = 0; q < 8; q++) {
                bf16 hb = __float2bfloat16(src[q]);
                hv[q] = __bfloat162float(hb);
                lv[q] = src[q] - hv[q];
            }
            ash[kc][0] = pk2(hv[0], hv[1]); ash[kc][1] = pk2(hv[2], hv[3]);
            ash[kc][2] = pk2(hv[4], hv[5]); ash[kc][3] = pk2(hv[6], hv[7]);
            asl[kc][0] = pk2(lv[0], lv[1]); asl[kc][1] = pk2(lv[2], lv[3]);
            asl[kc][2] = pk2(lv[4], lv[5]); asl[kc][3] = pk2(lv[6], lv[7]);
        }

#pragma unroll
        for (int kc = 0; kc < 4; kc++) {
            uint32_t bv[2][8][2];
#pragma unroll
            for (int p = 0; p < 2; p++)
#pragma unroll
                for (int na = 0; na < 4; na++) {
                    int row = kc * 16 + ((l >> 3) & 1) * 8 + (l & 7);
                    int col = na * 16 + (l >> 4) * 8;
                    uint32_t r4[4];
                    ldsm4t(r4, sb + RV(p) + (row * RST + col) * 2);
                    bv[p][na * 2][0] = r4[0]; bv[p][na * 2][1] = r4[1];
                    bv[p][na * 2 + 1][0] = r4[2]; bv[p][na * 2 + 1][1] = r4[3];
                }
#pragma unroll
            for (int ni = 0; ni < 8; ni++) mma_bf(oacc[ni], ash[kc], bv[0][ni]);
#pragma unroll
            for (int ni = 0; ni < 8; ni++) mma_bf(oacc[ni], ash[kc], bv[1][ni]);
#pragma unroll
            for (int ni = 0; ni < 8; ni++) mma_bf(oacc[ni], asl[kc], bv[0][ni]);
        }
    }

    // ---- fused state scan: state = sum_{c<ci} g128^(ci-1-c) * U_c ----
    __syncthreads();
    {
        const float g128 = exp2f(lg * 128.0f);
        const int row = tid >> 2;            // dk row 0..63
        const int c0 = (tid & 3) * 16;       // dv col group
        float st[16];
#pragma unroll
        for (int j = 0; j < 16; j++) st[j] = 0.f;
        for (int c = 0; c < ci; c++) {
            const float* U = g_U + ((size_t)bh * NCHUNK + c) * HD * HD + row * HD + c0;
#pragma unroll
            for (int j = 0; j < 16; j++) st[j] = st[j] * g128 + U[j];
        }
#pragma unroll
        for (int j = 0; j < 16; j += 2) {
            bf16 h0 = __float2bfloat16(st[j]), h1 = __float2bfloat16(st[j + 1]);
            float l0 = st[j] - __bfloat162float(h0);
            float l1 = st[j + 1] - __bfloat162float(h1);
            bf162 hv; hv.x = h0; hv.y = h1;
            *(bf162*)(sm + RK(0) + (row * RST + c0 + j) * 2) = hv;
            bf162 lv; lv.x = __float2bfloat16(l0); lv.y = __float2bfloat16(l1);
            *(bf162*)(sm + RK(1) + (row * RST + c0 + j) * 2) = lv;
        }
    }
    __syncthreads();

    float cacc[8][4];
#pragma unroll
    for (int ni = 0; ni < 8; ni++)
#pragma unroll
        for (int q = 0; q < 4; q++) cacc[ni][q] = 0.f;
#pragma unroll
    for (int kc = 0; kc < 4; kc++) {
        uint32_t bs[2][8][2];
#pragma unroll
        for (int p = 0; p < 2; p++)
#pragma unroll
            for (int na = 0; na < 4; na++) {
                int row = kc * 16 + ((l >> 3) & 1) * 8 + (l & 7);
                int col = na * 16 + (l >> 4) * 8;
                uint32_t r4[4];
                ldsm4t(r4, sb + RK(p) + (row * RST + col) * 2);
                bs[p][na * 2][0] = r4[0]; bs[p][na * 2][1] = r4[1];
                bs[p][na * 2 + 1][0] = r4[2]; bs[p][na * 2 + 1][1] = r4[3];
            }
#pragma unroll
        for (int ni = 0; ni < 8; ni++) mma_bf(cacc[ni], aq[0][kc], bs[0][ni]);
#pragma unroll
        for (int ni = 0; ni < 8; ni++) mma_bf(cacc[ni], aq[0][kc], bs[1][ni]);
#pragma unroll
        for (int ni = 0; ni < 8; ni++) mma_bf(cacc[ni], aq[1][kc], bs[0][ni]);
    }
    {
        const float w1 = 0.125f * exp2f(lg * (float)(il + 1));
        const float w2 = 0.125f * exp2f(lg * (float)(il + 9));
#pragma unroll
        for (int ni = 0; ni < 8; ni++) {
            oacc[ni][0] += w1 * cacc[ni][0];
            oacc[ni][1] += w1 * cacc[ni][1];
            oacc[ni][2] += w2 * cacc[ni][2];
            oacc[ni][3] += w2 * cacc[ni][3];
        }
    }

#pragma unroll
    for (int ni = 0; ni < 8; ni++) {
        int col = ni * 8 + 2 * tq;
        int r1 = t0 + il, r2 = r1 + 8;
        *(float2*)(g_O + (base + (size_t)r1 * HD + col)) = make_float2(oacc[ni][0], oacc[ni][1]);
        *(float2*)(g_O + (base + (size_t)r2 * HD + col)) = make_float2(oacc[ni][2], oacc[ni][3]);
    }
}

// ---------------------------------------------------------------------------
// GroupNorm: two-phase, parallel. Phase 1: 256 blocks write partial sums.
// Phase 2: 256 blocks normalize + split-write.
// ---------------------------------------------------------------------------
__global__ __launch_bounds__(256) void gn_reduce_kernel() {
    const int part = blockIdx.x, bh = blockIdx.y;
    const float* base = g_O + (size_t)bh * NT * HD + part * 16384;
    const int tid = threadIdx.x;
    double s1 = 0.0, s2 = 0.0;
#pragma unroll 8
    for (int k = 0; k < 64; k++) {
        float v = base[tid + 256 * k];
        s1 += v;
        s2 += (double)v * v;
    }
    __shared__ double r1[256], r2[256];
    r1[tid] = s1; r2[tid] = s2;
    __syncthreads();
    for (int s = 128; s > 0; s >>= 1) {
        if (tid < s) { r1[tid] += r1[tid + s]; r2[tid] += r2[tid + s]; }
        __syncthreads();
    }
    if (tid == 0) g_gnp[bh * 8 + part] = make_double2(r1[0], r2[0]);
}

__global__ __launch_bounds__(256) void gn_apply_kernel(const float* __restrict__ gnw,
                                                       const float* __restrict__ gnb) {
    const int part = blockIdx.x, bh = blockIdx.y;
    const int b = bh >> 4, h = bh & 15;
    double s1 = 0.0, s2 = 0.0;
#pragma unroll
    for (int p = 0; p < 8; p++) {
        double2 v = g_gnp[bh * 8 + p];
        s1 += v.x; s2 += v.y;
    }
    const double n = (double)(NT * HD);
    double mud = s1 / n;
    double var = s2 / n - mud * mud;
    const float mu = (float)mud;
    const float rs = (float)(1.0 / sqrt(var + 1e-5));

    const float* bsrc = g_O + (size_t)bh * NT * HD;
    const int tid = threadIdx.x;
#pragma unroll 8
    for (int k = 0; k < 64; k++) {
        int i = part * 16384 + tid + 256 * k;
        int t = i >> 6, d = i & 63;
        int c = h * 64 + d;
        float v = (bsrc[i] - mu) * rs * gnw[c] + gnb[c];
        size_t idx = ((size_t)b * NT + t) * NC + c;
        bf16 hv = __float2bfloat16(v);
        g_Ynh[idx] = hv;
        g_Ynl[idx] = __float2bfloat16(v - __bfloat162float(hv));
    }
}

// ---------------------------------------------------------------------------
// Launch. Launch #4 = retention_chunk (profiled slot).
// ---------------------------------------------------------------------------
extern "C" void kernel_launch(void* const* d_in, const int* in_sizes, int n_in,
                              void* d_out, int out_size) {
    const float* x   = (const float*)d_in[0];
    const float* Wq  = (const float*)d_in[1];
    const float* Wk  = (const float*)d_in[2];
    const float* Wv  = (const float*)d_in[3];
    const float* Wo  = (const float*)d_in[4];
    const float* gnw = (const float*)d_in[5];
    const float* gnb = (const float*)d_in[6];
    float* out = (float*)d_out;

    cudaFuncSetAttribute(gemm_mma<0>, cudaFuncAttributeMaxDynamicSharedMemorySize, GEMM_SMEM);
    cudaFuncSetAttribute(gemm_mma<1>, cudaFuncAttributeMaxDynamicSharedMemorySize, GEMM_SMEM);
    cudaFuncSetAttribute(chunk_state_kernel, cudaFuncAttributeMaxDynamicSharedMemorySize, CHUNK_SMEM);
    cudaFuncSetAttribute(retention_chunk_kernel, cudaFuncAttributeMaxDynamicSharedMemorySize, RET_SMEM);

    split_all_kernel<<<(NX4 + 4 * NW4) / 256, 256>>>(
        (const float4*)x, (const float4*)Wq, (const float4*)Wk,
        (const float4*)Wv, (const float4*)Wo);                                 // 1
    gemm_mma<0><<<dim3(MTOT / 128, NC / 128, 3), 256, GEMM_SMEM>>>(nullptr);   // 2
    chunk_state_kernel<<<dim3(NCHUNK, NB * NH), 128, CHUNK_SMEM>>>();          // 3
    retention_chunk_kernel<<<dim3(NCHUNK, NB * NH), 256, RET_SMEM>>>();        // 4 (profiled)
    gn_reduce_kernel<<<dim3(8, NB * NH), 256>>>();                             // 5
    gn_apply_kernel<<<dim3(8, NB * NH), 256>>>(gnw, gnb);                      // 6
    gemm_mma<1><<<dim3(MTOT / 128, NC / 128, 1), 256, GEMM_SMEM>>>(out);       // 7
}